// round 2
// baseline (speedup 1.0000x reference)
#include <cuda_runtime.h>
#include <math.h>

// ---------------- problem constants ----------------
#define HH      64      // heads
#define PP      64      // head dim
#define NST     128     // state dim
#define GG      8       // groups
#define DMODEL  2048
#define CSZ     256     // chunk size
#define LL      4096    // sequence length
#define INTER_  4096    // H*P
#define CONVDIM_ 6144   // INTER + 2*G*N
#define PROJ_   10304   // INTER + CONVDIM + H
#define NCH     16      // number of chunks
#define NBATCH  1024    // NCH * HH

// ---------------- scratch (static device globals; no runtime alloc) ----------------
__device__ float d_proj[(size_t)LL * PROJ_];       // 168.8 MB
__device__ float d_conv[(size_t)LL * CONVDIM_];    // 100.7 MB (post conv+silu)
__device__ float d_dt[(size_t)LL * HH];            // softplus(dt + bias)
__device__ float d_Acs[(size_t)HH * LL];           // per-head within-chunk inclusive cumsum of dt*A
__device__ float d_S[(size_t)NBATCH * CSZ * CSZ];  // 268 MB scores*Lmat
__device__ float d_xdt[(size_t)LL * INTER_];       // x * dt   [l][h*64+p]
__device__ float d_xdtd[(size_t)INTER_ * LL];      // (x*dt*decay) transposed [h*64+p][l]
__device__ float d_states[(size_t)NBATCH * PP * NST];
__device__ float d_prev[(size_t)NBATCH * PP * NST];
__device__ float d_Y[(size_t)LL * INTER_];
__device__ float d_norm[(size_t)LL * INTER_];

// ---------------- packed f32x2 helpers (FFMA2: 2x fp32 rate vs 3-reg FFMA) ----------------
__device__ __forceinline__ unsigned long long pack2(float lo, float hi) {
    unsigned long long r;
    asm("mov.b64 %0, {%1, %2};" : "=l"(r) : "f"(lo), "f"(hi));
    return r;
}
__device__ __forceinline__ void fma2(unsigned long long& d, unsigned long long a, unsigned long long b) {
    asm("fma.rn.f32x2 %0, %1, %2, %0;" : "+l"(d) : "l"(a), "l"(b));
}
__device__ __forceinline__ float2 unpack2(unsigned long long u) {
    float2 v;
    asm("mov.b64 {%0, %1}, %2;" : "=f"(v.x), "=f"(v.y) : "l"(u));
    return v;
}

// ============================================================================
// Big SGEMM: C[M,N] = A[M,K] * B[N,K]^T  (A,B row-major K-major). M%128==0, K%16==0.
// 128x128 tile, 16 K-slice, 256 threads, 8x8 microtile, packed FFMA2 inner loop.
// ============================================================================
__global__ __launch_bounds__(256) void sgemm_nt128(
    const float* __restrict__ A, const float* __restrict__ B,
    float* __restrict__ C, int M, int N, int K)
{
    __shared__ float As[16][128];
    __shared__ float Bs[16][128];
    const int tid = threadIdx.x;
    const int m0 = blockIdx.y * 128;
    const int n0 = blockIdx.x * 128;
    const int ty = tid >> 4, tx = tid & 15;
    const int lr = tid >> 2;            // 0..63
    const int lc = (tid & 3) << 2;      // 0,4,8,12

    unsigned long long accp[8][4];
#pragma unroll
    for (int i = 0; i < 8; i++)
#pragma unroll
        for (int j = 0; j < 4; j++) accp[i][j] = 0ull;

    for (int k0 = 0; k0 < K; k0 += 16) {
#pragma unroll
        for (int half = 0; half < 2; half++) {
            int r = lr + half * 64;
            float4 av = *(const float4*)(A + (size_t)(m0 + r) * K + k0 + lc);
            As[lc + 0][r] = av.x; As[lc + 1][r] = av.y;
            As[lc + 2][r] = av.z; As[lc + 3][r] = av.w;
            int n = n0 + r;
            float4 bv = make_float4(0.f, 0.f, 0.f, 0.f);
            if (n < N) bv = *(const float4*)(B + (size_t)n * K + k0 + lc);
            Bs[lc + 0][r] = bv.x; Bs[lc + 1][r] = bv.y;
            Bs[lc + 2][r] = bv.z; Bs[lc + 3][r] = bv.w;
        }
        __syncthreads();
#pragma unroll
        for (int k = 0; k < 16; k++) {
            float a[8];
            *(float4*)&a[0] = *(const float4*)&As[k][ty * 8];
            *(float4*)&a[4] = *(const float4*)&As[k][ty * 8 + 4];
            unsigned long long bp0 = *(const unsigned long long*)&Bs[k][tx * 8 + 0];
            unsigned long long bp1 = *(const unsigned long long*)&Bs[k][tx * 8 + 2];
            unsigned long long bp2 = *(const unsigned long long*)&Bs[k][tx * 8 + 4];
            unsigned long long bp3 = *(const unsigned long long*)&Bs[k][tx * 8 + 6];
#pragma unroll
            for (int i = 0; i < 8; i++) {
                unsigned long long ap = pack2(a[i], a[i]);
                fma2(accp[i][0], ap, bp0);
                fma2(accp[i][1], ap, bp1);
                fma2(accp[i][2], ap, bp2);
                fma2(accp[i][3], ap, bp3);
            }
        }
        __syncthreads();
    }
#pragma unroll
    for (int i = 0; i < 8; i++) {
        int m = m0 + ty * 8 + i;
        float cv[8];
#pragma unroll
        for (int j = 0; j < 4; j++) {
            float2 v = unpack2(accp[i][j]);
            cv[2 * j] = v.x; cv[2 * j + 1] = v.y;
        }
#pragma unroll
        for (int jv = 0; jv < 2; jv++) {
            int n = n0 + tx * 8 + jv * 4;
            if (n < N) {
                *(float4*)(C + (size_t)m * N + n) =
                    make_float4(cv[jv * 4], cv[jv * 4 + 1], cv[jv * 4 + 2], cv[jv * 4 + 3]);
            }
        }
    }
}

// ============================================================================
// dt = softplus(proj_dt + dt_bias)
// ============================================================================
__global__ void dt_kernel(const float* __restrict__ dt_bias) {
    int id = blockIdx.x * blockDim.x + threadIdx.x;
    if (id >= LL * HH) return;
    int l = id >> 6, h = id & 63;
    float v = d_proj[(size_t)l * PROJ_ + INTER_ + CONVDIM_ + h] + dt_bias[h];
    float sp = (v > 20.f) ? v : log1pf(expf(v));
    d_dt[id] = sp;
}

// ============================================================================
// Within-chunk inclusive cumsum of Abar = dt * A  ->  d_Acs[h][l]
// ============================================================================
__global__ void acs_kernel(const float* __restrict__ A_log) {
    int t = blockIdx.x * blockDim.x + threadIdx.x;
    if (t >= NCH * HH) return;
    int h = t & 63, c = t >> 6;
    float Ah = -expf(A_log[h]);
    float run = 0.f;
    for (int s = 0; s < CSZ; s++) {
        run += d_dt[(size_t)(c * CSZ + s) * HH + h] * Ah;
        d_Acs[(size_t)h * LL + c * CSZ + s] = run;
    }
}

// ============================================================================
// Causal depthwise conv (K=4) + bias + SiLU
// ============================================================================
__global__ void conv_kernel(const float* __restrict__ conv_w, const float* __restrict__ conv_b) {
    int id = blockIdx.x * blockDim.x + threadIdx.x;
    if (id >= LL * CONVDIM_) return;
    int l = id / CONVDIM_, cc = id % CONVDIM_;
    float acc = conv_b[cc];
#pragma unroll
    for (int k = 0; k < 4; k++) {
        int li = l - 3 + k;
        if (li >= 0) acc += conv_w[cc * 4 + k] * d_proj[(size_t)li * PROJ_ + INTER_ + cc];
    }
    d_conv[id] = acc / (1.f + __expf(-acc));   // silu
}

// ============================================================================
// xdt = x * dt     [l][h*64+p]
// ============================================================================
__global__ void xdt_kernel() {
    int id = blockIdx.x * blockDim.x + threadIdx.x;
    if (id >= LL * INTER_) return;
    int l = id >> 12, hp = id & 4095, h = hp >> 6;
    d_xdt[id] = d_conv[(size_t)l * CONVDIM_ + hp] * d_dt[(size_t)l * HH + h];
}

// ============================================================================
// xdtd = transpose(xdt) * exp(Acs[chunk_end] - Acs[l])   -> [h*64+p][l]
// ============================================================================
__global__ void xdtd_kernel() {
    __shared__ float tile[32][33];
    int x = blockIdx.x * 32 + threadIdx.x;   // hp
    int y0 = blockIdx.y * 32;                // l base
    for (int j = threadIdx.y; j < 32; j += 8)
        tile[j][threadIdx.x] = d_xdt[(size_t)(y0 + j) * INTER_ + x];
    __syncthreads();
    int l = y0 + threadIdx.x;
    int lastl = l | (CSZ - 1);
    for (int j = threadIdx.y; j < 32; j += 8) {
        int hp = blockIdx.x * 32 + j;
        int h = hp >> 6;
        float last = d_Acs[(size_t)h * LL + lastl];
        float cur = d_Acs[(size_t)h * LL + l];
        d_xdtd[(size_t)hp * LL + l] = tile[threadIdx.x][j] * __expf(last - cur);
    }
}

// ============================================================================
// scores*Lmat: S[l,s] = (s<=l) * exp(Acs[l]-Acs[s]) * sum_n C[l,n]*B[s,n]
// batched over (chunk,head), 64x64 tiles, K=128
// ============================================================================
__global__ __launch_bounds__(256) void scores_kernel() {
    const int z = blockIdx.z;
    const int c = z >> 6, h = z & 63, g = h >> 3;
    const int m0 = blockIdx.y * 64;   // l
    const int n0 = blockIdx.x * 64;   // s
    float* Sb = d_S + (size_t)z * (CSZ * CSZ);
    const int tid = threadIdx.x;
    if (n0 > m0 + 63) {               // strictly above diagonal: all masked to zero
        for (int idx = tid; idx < 1024; idx += 256) {
            int r = idx >> 4, c4 = (idx & 15) << 2;
            *(float4*)(Sb + (m0 + r) * CSZ + n0 + c4) = make_float4(0.f, 0.f, 0.f, 0.f);
        }
        return;
    }
    const float* Ab = d_conv + (size_t)(c * CSZ) * CONVDIM_ + (INTER_ + GG * NST) + g * NST; // C
    const float* Bb = d_conv + (size_t)(c * CSZ) * CONVDIM_ + INTER_ + g * NST;              // B
    __shared__ float As[16][64], Bs[16][64];
    const int ty = tid >> 4, tx = tid & 15;
    const int lr = tid >> 2, lc = (tid & 3) << 2;
    float acc[4][4];
#pragma unroll
    for (int i = 0; i < 4; i++)
#pragma unroll
        for (int j = 0; j < 4; j++) acc[i][j] = 0.f;
    for (int k0 = 0; k0 < NST; k0 += 16) {
        float4 av = *(const float4*)(Ab + (size_t)(m0 + lr) * CONVDIM_ + k0 + lc);
        As[lc + 0][lr] = av.x; As[lc + 1][lr] = av.y; As[lc + 2][lr] = av.z; As[lc + 3][lr] = av.w;
        float4 bv = *(const float4*)(Bb + (size_t)(n0 + lr) * CONVDIM_ + k0 + lc);
        Bs[lc + 0][lr] = bv.x; Bs[lc + 1][lr] = bv.y; Bs[lc + 2][lr] = bv.z; Bs[lc + 3][lr] = bv.w;
        __syncthreads();
#pragma unroll
        for (int k = 0; k < 16; k++) {
            float a[4], b[4];
            *(float4*)a = *(const float4*)&As[k][ty * 4];
            *(float4*)b = *(const float4*)&Bs[k][tx * 4];
#pragma unroll
            for (int i = 0; i < 4; i++)
#pragma unroll
                for (int j = 0; j < 4; j++) acc[i][j] += a[i] * b[j];
        }
        __syncthreads();
    }
    const float* acs = d_Acs + (size_t)h * LL + c * CSZ;
#pragma unroll
    for (int i = 0; i < 4; i++) {
        int l = m0 + ty * 4 + i;
        float al = acs[l];
#pragma unroll
        for (int j = 0; j < 4; j++) {
            int s = n0 + tx * 4 + j;
            float v = 0.f;
            if (s <= l) v = acc[i][j] * __expf(al - acs[s]);
            Sb[l * CSZ + s] = v;
        }
    }
}

// ============================================================================
// Y_diag[l,p] = sum_s S[l,s] * xdt[s,p]     (writes d_Y)
// ============================================================================
__global__ __launch_bounds__(256) void ydiag_kernel() {
    const int z = blockIdx.z;
    const int c = z >> 6, h = z & 63;
    const int m0 = blockIdx.y * 64;
    const float* Ab = d_S + (size_t)z * (CSZ * CSZ);                    // lda = 256
    const float* Bb = d_xdt + (size_t)(c * CSZ) * INTER_ + h * PP;      // ldb = 4096 (NN)
    __shared__ float As[16][64], Bs[16][64];
    const int tid = threadIdx.x;
    const int ty = tid >> 4, tx = tid & 15;
    const int lr = tid >> 2, lc = (tid & 3) << 2;
    const int kr = tid >> 4, nc = (tid & 15) << 2;
    float acc[4][4];
#pragma unroll
    for (int i = 0; i < 4; i++)
#pragma unroll
        for (int j = 0; j < 4; j++) acc[i][j] = 0.f;
    for (int k0 = 0; k0 < CSZ; k0 += 16) {
        float4 av = *(const float4*)(Ab + (size_t)(m0 + lr) * CSZ + k0 + lc);
        As[lc + 0][lr] = av.x; As[lc + 1][lr] = av.y; As[lc + 2][lr] = av.z; As[lc + 3][lr] = av.w;
        float4 bv = *(const float4*)(Bb + (size_t)(k0 + kr) * INTER_ + nc);
        *(float4*)&Bs[kr][nc] = bv;
        __syncthreads();
#pragma unroll
        for (int k = 0; k < 16; k++) {
            float a[4], b[4];
            *(float4*)a = *(const float4*)&As[k][ty * 4];
            *(float4*)b = *(const float4*)&Bs[k][tx * 4];
#pragma unroll
            for (int i = 0; i < 4; i++)
#pragma unroll
                for (int j = 0; j < 4; j++) acc[i][j] += a[i] * b[j];
        }
        __syncthreads();
    }
#pragma unroll
    for (int i = 0; i < 4; i++) {
        int l = m0 + ty * 4 + i;
        *(float4*)(d_Y + (size_t)(c * CSZ + l) * INTER_ + h * PP + tx * 4) =
            make_float4(acc[i][0], acc[i][1], acc[i][2], acc[i][3]);
    }
}

// ============================================================================
// states[p,n] = sum_s xdtd[p,s] * B[s,n]
// ============================================================================
__global__ __launch_bounds__(256) void states_kernel() {
    const int z = blockIdx.z;
    const int c = z >> 6, h = z & 63, g = h >> 3;
    const int n0 = blockIdx.x * 64;
    const float* Ab = d_xdtd + (size_t)(h * PP) * LL + c * CSZ;                 // lda = 4096
    const float* Bb = d_conv + (size_t)(c * CSZ) * CONVDIM_ + INTER_ + g * NST; // ldb = 6144 (NN)
    __shared__ float As[16][64], Bs[16][64];
    const int tid = threadIdx.x;
    const int ty = tid >> 4, tx = tid & 15;
    const int lr = tid >> 2, lc = (tid & 3) << 2;
    const int kr = tid >> 4, nc = (tid & 15) << 2;
    float acc[4][4];
#pragma unroll
    for (int i = 0; i < 4; i++)
#pragma unroll
        for (int j = 0; j < 4; j++) acc[i][j] = 0.f;
    for (int k0 = 0; k0 < CSZ; k0 += 16) {
        float4 av = *(const float4*)(Ab + (size_t)lr * LL + k0 + lc);
        As[lc + 0][lr] = av.x; As[lc + 1][lr] = av.y; As[lc + 2][lr] = av.z; As[lc + 3][lr] = av.w;
        float4 bv = *(const float4*)(Bb + (size_t)(k0 + kr) * CONVDIM_ + n0 + nc);
        *(float4*)&Bs[kr][nc] = bv;
        __syncthreads();
#pragma unroll
        for (int k = 0; k < 16; k++) {
            float a[4], b[4];
            *(float4*)a = *(const float4*)&As[k][ty * 4];
            *(float4*)b = *(const float4*)&Bs[k][tx * 4];
#pragma unroll
            for (int i = 0; i < 4; i++)
#pragma unroll
                for (int j = 0; j < 4; j++) acc[i][j] += a[i] * b[j];
        }
        __syncthreads();
    }
#pragma unroll
    for (int i = 0; i < 4; i++) {
        int p = ty * 4 + i;
        *(float4*)(d_states + ((size_t)z * PP + p) * NST + n0 + tx * 4) =
            make_float4(acc[i][0], acc[i][1], acc[i][2], acc[i][3]);
    }
}

// ============================================================================
// Inter-chunk state recurrence: prev[c] = carry; carry = carry*chunk_decay + states[c]
// ============================================================================
__global__ void state_scan_kernel() {
    int t = blockIdx.x * blockDim.x + threadIdx.x;
    if (t >= HH * PP * NST) return;
    int n = t & 127, p = (t >> 7) & 63, h = t >> 13;
    float prev = 0.f;
#pragma unroll
    for (int c = 0; c < NCH; c++) {
        size_t idx = ((size_t)(c * HH + h) * PP + p) * NST + n;
        d_prev[idx] = prev;
        float cd = __expf(d_Acs[(size_t)h * LL + c * CSZ + 255]);
        prev = prev * cd + d_states[idx];
    }
}

// ============================================================================
// Y_off + combine: d_Y[l,p] += exp(Acs[l]) * sum_n C[l,n]*prev[p,n] + D[h]*x[l,p]
// ============================================================================
__global__ __launch_bounds__(256) void yoff_kernel(const float* __restrict__ Dvec) {
    const int z = blockIdx.z;
    const int c = z >> 6, h = z & 63, g = h >> 3;
    const int m0 = blockIdx.y * 64;
    const float* Ab = d_conv + (size_t)(c * CSZ) * CONVDIM_ + (INTER_ + GG * NST) + g * NST; // C, lda=6144
    const float* Bb = d_prev + (size_t)z * PP * NST;                                          // ldb=128 (NT)
    __shared__ float As[16][64], Bs[16][64];
    const int tid = threadIdx.x;
    const int ty = tid >> 4, tx = tid & 15;
    const int lr = tid >> 2, lc = (tid & 3) << 2;
    float acc[4][4];
#pragma unroll
    for (int i = 0; i < 4; i++)
#pragma unroll
        for (int j = 0; j < 4; j++) acc[i][j] = 0.f;
    for (int k0 = 0; k0 < NST; k0 += 16) {
        float4 av = *(const float4*)(Ab + (size_t)(m0 + lr) * CONVDIM_ + k0 + lc);
        As[lc + 0][lr] = av.x; As[lc + 1][lr] = av.y; As[lc + 2][lr] = av.z; As[lc + 3][lr] = av.w;
        float4 bv = *(const float4*)(Bb + (size_t)lr * NST + k0 + lc);
        Bs[lc + 0][lr] = bv.x; Bs[lc + 1][lr] = bv.y; Bs[lc + 2][lr] = bv.z; Bs[lc + 3][lr] = bv.w;
        __syncthreads();
#pragma unroll
        for (int k = 0; k < 16; k++) {
            float a[4], b[4];
            *(float4*)a = *(const float4*)&As[k][ty * 4];
            *(float4*)b = *(const float4*)&Bs[k][tx * 4];
#pragma unroll
            for (int i = 0; i < 4; i++)
#pragma unroll
                for (int j = 0; j < 4; j++) acc[i][j] += a[i] * b[j];
        }
        __syncthreads();
    }
    const float* acs = d_Acs + (size_t)h * LL + c * CSZ;
    float Dv = Dvec[h];
#pragma unroll
    for (int i = 0; i < 4; i++) {
        int l = m0 + ty * 4 + i;
        float sd = __expf(acs[l]);
        int gl = c * CSZ + l;
#pragma unroll
        for (int j = 0; j < 4; j++) {
            int p = tx * 4 + j;
            size_t xi = (size_t)gl * CONVDIM_ + h * PP + p;
            size_t yi = (size_t)gl * INTER_ + h * PP + p;
            d_Y[yi] = d_Y[yi] + acc[i][j] * sd + Dv * d_conv[xi];
        }
    }
}

// ============================================================================
// gated group RMS norm: g = Y*silu(gate); per 512-group rms; *norm_weight
// ============================================================================
__global__ __launch_bounds__(256) void norm_kernel(const float* __restrict__ norm_weight) {
    __shared__ float gbuf[INTER_];
    __shared__ float rs[GG];
    int l = blockIdx.x, tid = threadIdx.x;
    for (int i = tid; i < INTER_; i += 256) {
        float y = d_Y[(size_t)l * INTER_ + i];
        float gt = d_proj[(size_t)l * PROJ_ + i];
        float sg = 1.f / (1.f + __expf(-gt));
        gbuf[i] = y * gt * sg;
    }
    __syncthreads();
    int w = tid >> 5, lane = tid & 31;
    float ss = 0.f;
    for (int j = lane; j < 512; j += 32) { float v = gbuf[w * 512 + j]; ss += v * v; }
#pragma unroll
    for (int o = 16; o > 0; o >>= 1) ss += __shfl_xor_sync(0xffffffffu, ss, o);
    if (lane == 0) rs[w] = rsqrtf(ss * (1.f / 512.f) + 1e-5f);
    __syncthreads();
    for (int i = tid; i < INTER_; i += 256)
        d_norm[(size_t)l * INTER_ + i] = gbuf[i] * rs[i >> 9] * norm_weight[i];
}

// ============================================================================
extern "C" void kernel_launch(void* const* d_in, const int* in_sizes, int n_in,
                              void* d_out, int out_size) {
    (void)in_sizes; (void)n_in; (void)out_size;
    const float* hidden      = (const float*)d_in[0];
    const float* W_in        = (const float*)d_in[1];
    const float* conv_w      = (const float*)d_in[2];
    const float* conv_b      = (const float*)d_in[3];
    const float* dt_bias     = (const float*)d_in[4];
    const float* A_log       = (const float*)d_in[5];
    const float* Dvec        = (const float*)d_in[6];
    const float* norm_weight = (const float*)d_in[7];
    const float* W_out       = (const float*)d_in[8];
    float* out = (float*)d_out;

    float *p_proj = nullptr, *p_norm = nullptr;
    cudaGetSymbolAddress((void**)&p_proj, d_proj);
    cudaGetSymbolAddress((void**)&p_norm, d_norm);

    // 1) input projection: proj[L, PROJ] = hidden * W_in^T
    {
        dim3 grid((PROJ_ + 127) / 128, LL / 128);
        sgemm_nt128<<<grid, 256>>>(hidden, W_in, p_proj, LL, PROJ_, DMODEL);
    }
    // 2) dt softplus; 3) per-chunk cumsum of dt*A
    dt_kernel<<<(LL * HH) / 256, 256>>>(dt_bias);
    acs_kernel<<<(NCH * HH + 255) / 256, 256>>>(A_log);
    // 4) depthwise conv + silu
    conv_kernel<<<(LL * CONVDIM_) / 256, 256>>>(conv_w, conv_b);
    // 5) xdt, 6) decay-weighted transpose
    xdt_kernel<<<(LL * INTER_) / 256, 256>>>();
    {
        dim3 grid(INTER_ / 32, LL / 32);
        xdtd_kernel<<<grid, dim3(32, 8)>>>();
    }
    // 7) intra-chunk scores with causal decay mask
    scores_kernel<<<dim3(4, 4, NBATCH), 256>>>();
    // 8) Y_diag
    ydiag_kernel<<<dim3(1, 4, NBATCH), 256>>>();
    // 9) per-chunk states
    states_kernel<<<dim3(2, 1, NBATCH), 256>>>();
    // 10) inter-chunk recurrence
    state_scan_kernel<<<(HH * PP * NST) / 256, 256>>>();
    // 11) Y_off + D*x combine
    yoff_kernel<<<dim3(1, 4, NBATCH), 256>>>(Dvec);
    // 12) gated group RMS norm
    norm_kernel<<<LL, 256>>>(norm_weight);
    // 13) output projection
    {
        dim3 grid(DMODEL / 128, LL / 128);
        sgemm_nt128<<<grid, 256>>>(p_norm, W_out, out, LL, DMODEL, INTER_);
    }
}

// round 4
// speedup vs baseline: 1.7861x; 1.7861x over previous
#include <cuda_runtime.h>
#include <cuda_bf16.h>
#include <math.h>
#include <stdint.h>

// ---------------- problem constants ----------------
#define HH      64
#define PP      64
#define NST     128
#define GG      8
#define DMODEL  2048
#define CSZ     256
#define LL      4096
#define INTER_  4096
#define CONVDIM_ 6144
#define PROJ_   10304
#define NCH     16
#define NBATCH  1024

// ---------------- scratch ----------------
__device__ float d_proj[(size_t)LL * PROJ_];
__device__ float d_conv[(size_t)LL * CONVDIM_];
__device__ float d_dt[(size_t)LL * HH];
__device__ float d_Acs[(size_t)HH * LL];
__device__ float d_S[(size_t)NBATCH * CSZ * CSZ];
__device__ float d_xdt[(size_t)LL * INTER_];
__device__ float d_xdtd[(size_t)INTER_ * LL];
__device__ float d_states[(size_t)NBATCH * PP * NST];
__device__ float d_prev[(size_t)NBATCH * PP * NST];
__device__ float d_Y[(size_t)LL * INTER_];
__device__ float d_norm[(size_t)LL * INTER_];

// bf16 hi/lo split buffers for tensor-core GEMMs
__device__ __nv_bfloat16 d_A1hi[(size_t)LL * DMODEL];
__device__ __nv_bfloat16 d_A1lo[(size_t)LL * DMODEL];
__device__ __nv_bfloat16 d_W1hi[(size_t)PROJ_ * DMODEL];
__device__ __nv_bfloat16 d_W1lo[(size_t)PROJ_ * DMODEL];
__device__ __nv_bfloat16 d_A2hi[(size_t)LL * INTER_];
__device__ __nv_bfloat16 d_A2lo[(size_t)LL * INTER_];
__device__ __nv_bfloat16 d_W2hi[(size_t)DMODEL * INTER_];
__device__ __nv_bfloat16 d_W2lo[(size_t)DMODEL * INTER_];

__device__ __forceinline__ uint32_t smem_u32(const void* p) {
    uint32_t a;
    asm("{ .reg .u64 t; cvta.to.shared.u64 t, %1; cvt.u32.u64 %0, t; }" : "=r"(a) : "l"(p));
    return a;
}

// ============================================================================
// Split-bf16 tensor-core GEMM via mma.sync (legacy HMMA path, valid on sm_100):
// C[M,N] = Ahi*Bhi^T + Alo*Bhi^T + Ahi*Blo^T
// A*: [M,K] bf16 row-major, B*: [N,K] bf16 row-major.
// 128x128 block tile, 8 warps (4x2; warp tile 32x64), K-chunk 32,
// 3-stage cp.async pipeline, padded smem rows (stride 80B, ldmatrix-conflict-free).
// ============================================================================
#define MM_STAGES 3
#define MM_ROWB   80                       // bytes per smem row (32 bf16 + 8 pad)
#define MM_ABYTES (128 * MM_ROWB)          // 10240 per operand per stage
#define MM_SSTAGE (2 * MM_ABYTES)          // 20480
#define MM_SMEM   (MM_STAGES * MM_SSTAGE)  // 61440

__global__ __launch_bounds__(256) void gemm_mma(
    const __nv_bfloat16* __restrict__ Ahi, const __nv_bfloat16* __restrict__ Alo,
    const __nv_bfloat16* __restrict__ Bhi, const __nv_bfloat16* __restrict__ Blo,
    float* __restrict__ C, int M, int N, int K)
{
    extern __shared__ char smem[];
    const int tid  = threadIdx.x;
    const int wid  = tid >> 5;
    const int lane = tid & 31;
    const int m0 = blockIdx.x * 128;
    const int n0 = blockIdx.y * 128;
    const int wm = (wid & 3) * 32;     // warp m offset in tile
    const int wn = (wid >> 2) * 64;    // warp n offset in tile
    const uint32_t sbase = smem_u32(smem);

    const int KB = K >> 5;             // 32-wide chunks per segment
    const int NC = 3 * KB;             // 3 split segments

    float acc[2][8][4];
#pragma unroll
    for (int i = 0; i < 2; i++)
#pragma unroll
        for (int j = 0; j < 8; j++)
#pragma unroll
            for (int t = 0; t < 4; t++) acc[i][j][t] = 0.f;

    // per-thread load slots: 512 16B items per operand / 256 threads = 2 each
    const int it0 = tid, it1 = tid + 256;
    const int ar0 = it0 >> 2, ac0 = (it0 & 3) << 4;   // row, byte-col
    const int ar1 = it1 >> 2, ac1 = (it1 & 3) << 4;

    auto issue = [&](int j) {
        const int s = j % MM_STAGES;
        const uint32_t As = sbase + s * MM_SSTAGE;
        const uint32_t Bs = As + MM_ABYTES;
        const int seg = j / KB;
        const int kk = j - seg * KB;
        const __nv_bfloat16* Ag = (seg == 1) ? Alo : Ahi;
        const __nv_bfloat16* Bg = (seg == 2) ? Blo : Bhi;
        const size_t kof = (size_t)kk * 32;
        {
            const void* g0 = Ag + (size_t)(m0 + ar0) * K + kof + (ac0 >> 1);
            const void* g1 = Ag + (size_t)(m0 + ar1) * K + kof + (ac1 >> 1);
            asm volatile("cp.async.cg.shared.global [%0], [%1], 16;\n"
                         :: "r"(As + ar0 * MM_ROWB + ac0), "l"(g0));
            asm volatile("cp.async.cg.shared.global [%0], [%1], 16;\n"
                         :: "r"(As + ar1 * MM_ROWB + ac1), "l"(g1));
        }
        {
            int nn0 = n0 + ar0, nn1 = n0 + ar1;
            int p0 = (nn0 < N) ? 16 : 0;
            int p1 = (nn1 < N) ? 16 : 0;
            if (nn0 >= N) nn0 = 0;
            if (nn1 >= N) nn1 = 0;
            const void* g0 = Bg + (size_t)nn0 * K + kof + (ac0 >> 1);
            const void* g1 = Bg + (size_t)nn1 * K + kof + (ac1 >> 1);
            asm volatile("cp.async.cg.shared.global [%0], [%1], 16, %2;\n"
                         :: "r"(Bs + ar0 * MM_ROWB + ac0), "l"(g0), "r"(p0));
            asm volatile("cp.async.cg.shared.global [%0], [%1], 16, %2;\n"
                         :: "r"(Bs + ar1 * MM_ROWB + ac1), "l"(g1), "r"(p1));
        }
    };

    const int quad = lane >> 3, qj = lane & 7;

    auto compute = [&](int i) {
        const int s = i % MM_STAGES;
        const uint32_t As = sbase + s * MM_SSTAGE;
        const uint32_t Bs = As + MM_ABYTES;
#pragma unroll
        for (int k16 = 0; k16 < 2; k16++) {
            const int k0 = k16 * 16;
            uint32_t a[2][4];
#pragma unroll
            for (int mt = 0; mt < 2; mt++) {
                int row = wm + mt * 16 + ((quad & 1) ? 8 : 0) + qj;
                int kel = k0 + ((quad & 2) ? 8 : 0);
                uint32_t addr = As + row * MM_ROWB + kel * 2;
                asm volatile("ldmatrix.sync.aligned.m8n8.x4.shared.b16 {%0,%1,%2,%3}, [%4];"
                             : "=r"(a[mt][0]), "=r"(a[mt][1]), "=r"(a[mt][2]), "=r"(a[mt][3])
                             : "r"(addr));
            }
            uint32_t b[8][2];
#pragma unroll
            for (int np = 0; np < 4; np++) {
                int row = wn + np * 16 + ((quad & 2) ? 8 : 0) + qj;
                int kel = k0 + ((quad & 1) ? 8 : 0);
                uint32_t addr = Bs + row * MM_ROWB + kel * 2;
                uint32_t r0, r1, r2, r3;
                asm volatile("ldmatrix.sync.aligned.m8n8.x4.shared.b16 {%0,%1,%2,%3}, [%4];"
                             : "=r"(r0), "=r"(r1), "=r"(r2), "=r"(r3) : "r"(addr));
                b[np * 2][0] = r0; b[np * 2][1] = r1;
                b[np * 2 + 1][0] = r2; b[np * 2 + 1][1] = r3;
            }
#pragma unroll
            for (int mt = 0; mt < 2; mt++)
#pragma unroll
                for (int nt = 0; nt < 8; nt++) {
                    asm volatile(
                        "mma.sync.aligned.m16n8k16.row.col.f32.bf16.bf16.f32 "
                        "{%0,%1,%2,%3}, {%4,%5,%6,%7}, {%8,%9}, {%0,%1,%2,%3};"
                        : "+f"(acc[mt][nt][0]), "+f"(acc[mt][nt][1]),
                          "+f"(acc[mt][nt][2]), "+f"(acc[mt][nt][3])
                        : "r"(a[mt][0]), "r"(a[mt][1]), "r"(a[mt][2]), "r"(a[mt][3]),
                          "r"(b[nt][0]), "r"(b[nt][1]));
                }
        }
    };

    issue(0);
    asm volatile("cp.async.commit_group;\n" ::: "memory");
    issue(1);
    asm volatile("cp.async.commit_group;\n" ::: "memory");

    for (int i = 0; i < NC; i++) {
        if (i + 2 < NC) issue(i + 2);
        asm volatile("cp.async.commit_group;\n" ::: "memory");
        asm volatile("cp.async.wait_group 2;\n" ::: "memory");
        __syncthreads();
        compute(i);
        __syncthreads();
    }

    // epilogue
    const int g = lane >> 2, t4 = lane & 3;
#pragma unroll
    for (int mt = 0; mt < 2; mt++) {
#pragma unroll
        for (int nt = 0; nt < 8; nt++) {
            int m = m0 + wm + mt * 16 + g;
            int n = n0 + wn + nt * 8 + t4 * 2;
            if (n < N) {
                *(float2*)(C + (size_t)m * N + n) = make_float2(acc[mt][nt][0], acc[mt][nt][1]);
                *(float2*)(C + (size_t)(m + 8) * N + n) = make_float2(acc[mt][nt][2], acc[mt][nt][3]);
            }
        }
    }
}

// ============================================================================
// fp32 -> (bf16 hi, bf16 lo) split, vectorized
// ============================================================================
__global__ void cvt_kernel(const float* __restrict__ src, __nv_bfloat16* __restrict__ hi,
                           __nv_bfloat16* __restrict__ lo, int n4) {
    int i = blockIdx.x * blockDim.x + threadIdx.x;
    if (i >= n4) return;
    float4 v = ((const float4*)src)[i];
    __nv_bfloat16 h0 = __float2bfloat16_rn(v.x);
    __nv_bfloat16 h1 = __float2bfloat16_rn(v.y);
    __nv_bfloat16 h2 = __float2bfloat16_rn(v.z);
    __nv_bfloat16 h3 = __float2bfloat16_rn(v.w);
    __nv_bfloat16 l0 = __float2bfloat16_rn(v.x - __bfloat162float(h0));
    __nv_bfloat16 l1 = __float2bfloat16_rn(v.y - __bfloat162float(h1));
    __nv_bfloat16 l2 = __float2bfloat16_rn(v.z - __bfloat162float(h2));
    __nv_bfloat16 l3 = __float2bfloat16_rn(v.w - __bfloat162float(h3));
    ((__nv_bfloat162*)hi)[2 * i]     = __nv_bfloat162(h0, h1);
    ((__nv_bfloat162*)hi)[2 * i + 1] = __nv_bfloat162(h2, h3);
    ((__nv_bfloat162*)lo)[2 * i]     = __nv_bfloat162(l0, l1);
    ((__nv_bfloat162*)lo)[2 * i + 1] = __nv_bfloat162(l2, l3);
}

// ============================================================================
// SSM mid-section kernels
// ============================================================================
__global__ void dt_kernel(const float* __restrict__ dt_bias) {
    int id = blockIdx.x * blockDim.x + threadIdx.x;
    if (id >= LL * HH) return;
    int l = id >> 6, h = id & 63;
    float v = d_proj[(size_t)l * PROJ_ + INTER_ + CONVDIM_ + h] + dt_bias[h];
    float sp = (v > 20.f) ? v : log1pf(expf(v));
    d_dt[id] = sp;
}

__global__ void acs_kernel(const float* __restrict__ A_log) {
    int t = blockIdx.x * blockDim.x + threadIdx.x;
    if (t >= NCH * HH) return;
    int h = t & 63, c = t >> 6;
    float Ah = -expf(A_log[h]);
    float run = 0.f;
    for (int s = 0; s < CSZ; s++) {
        run += d_dt[(size_t)(c * CSZ + s) * HH + h] * Ah;
        d_Acs[(size_t)h * LL + c * CSZ + s] = run;
    }
}

__global__ void conv_kernel(const float* __restrict__ conv_w, const float* __restrict__ conv_b) {
    int id = blockIdx.x * blockDim.x + threadIdx.x;
    if (id >= LL * CONVDIM_) return;
    int l = id / CONVDIM_, cc = id % CONVDIM_;
    float acc = conv_b[cc];
#pragma unroll
    for (int k = 0; k < 4; k++) {
        int li = l - 3 + k;
        if (li >= 0) acc += conv_w[cc * 4 + k] * d_proj[(size_t)li * PROJ_ + INTER_ + cc];
    }
    d_conv[id] = acc / (1.f + __expf(-acc));
}

__global__ void xdt_kernel() {
    int id = blockIdx.x * blockDim.x + threadIdx.x;
    if (id >= LL * INTER_) return;
    int l = id >> 12, hp = id & 4095, h = hp >> 6;
    d_xdt[id] = d_conv[(size_t)l * CONVDIM_ + hp] * d_dt[(size_t)l * HH + h];
}

__global__ void xdtd_kernel() {
    __shared__ float tile[32][33];
    int x = blockIdx.x * 32 + threadIdx.x;
    int y0 = blockIdx.y * 32;
    for (int j = threadIdx.y; j < 32; j += 8)
        tile[j][threadIdx.x] = d_xdt[(size_t)(y0 + j) * INTER_ + x];
    __syncthreads();
    int l = y0 + threadIdx.x;
    int lastl = l | (CSZ - 1);
    for (int j = threadIdx.y; j < 32; j += 8) {
        int hp = blockIdx.x * 32 + j;
        int h = hp >> 6;
        float last = d_Acs[(size_t)h * LL + lastl];
        float cur = d_Acs[(size_t)h * LL + l];
        d_xdtd[(size_t)hp * LL + l] = tile[threadIdx.x][j] * __expf(last - cur);
    }
}

__global__ __launch_bounds__(256) void scores_kernel() {
    const int z = blockIdx.z;
    const int c = z >> 6, h = z & 63, g = h >> 3;
    const int m0 = blockIdx.y * 64;
    const int n0 = blockIdx.x * 64;
    float* Sb = d_S + (size_t)z * (CSZ * CSZ);
    const int tid = threadIdx.x;
    if (n0 > m0 + 63) {
        for (int idx = tid; idx < 1024; idx += 256) {
            int r = idx >> 4, c4 = (idx & 15) << 2;
            *(float4*)(Sb + (m0 + r) * CSZ + n0 + c4) = make_float4(0.f, 0.f, 0.f, 0.f);
        }
        return;
    }
    const float* Ab = d_conv + (size_t)(c * CSZ) * CONVDIM_ + (INTER_ + GG * NST) + g * NST;
    const float* Bb = d_conv + (size_t)(c * CSZ) * CONVDIM_ + INTER_ + g * NST;
    __shared__ float As[16][64], Bs[16][64];
    const int ty = tid >> 4, tx = tid & 15;
    const int lr = tid >> 2, lc = (tid & 3) << 2;
    float acc[4][4];
#pragma unroll
    for (int i = 0; i < 4; i++)
#pragma unroll
        for (int j = 0; j < 4; j++) acc[i][j] = 0.f;
    for (int k0 = 0; k0 < NST; k0 += 16) {
        float4 av = *(const float4*)(Ab + (size_t)(m0 + lr) * CONVDIM_ + k0 + lc);
        As[lc + 0][lr] = av.x; As[lc + 1][lr] = av.y; As[lc + 2][lr] = av.z; As[lc + 3][lr] = av.w;
        float4 bv = *(const float4*)(Bb + (size_t)(n0 + lr) * CONVDIM_ + k0 + lc);
        Bs[lc + 0][lr] = bv.x; Bs[lc + 1][lr] = bv.y; Bs[lc + 2][lr] = bv.z; Bs[lc + 3][lr] = bv.w;
        __syncthreads();
#pragma unroll
        for (int k = 0; k < 16; k++) {
            float a[4], b[4];
            *(float4*)a = *(const float4*)&As[k][ty * 4];
            *(float4*)b = *(const float4*)&Bs[k][tx * 4];
#pragma unroll
            for (int i = 0; i < 4; i++)
#pragma unroll
                for (int j = 0; j < 4; j++) acc[i][j] += a[i] * b[j];
        }
        __syncthreads();
    }
    const float* acs = d_Acs + (size_t)h * LL + c * CSZ;
#pragma unroll
    for (int i = 0; i < 4; i++) {
        int l = m0 + ty * 4 + i;
        float al = acs[l];
#pragma unroll
        for (int j = 0; j < 4; j++) {
            int s = n0 + tx * 4 + j;
            float v = 0.f;
            if (s <= l) v = acc[i][j] * __expf(al - acs[s]);
            Sb[l * CSZ + s] = v;
        }
    }
}

__global__ __launch_bounds__(256) void ydiag_kernel() {
    const int z = blockIdx.z;
    const int c = z >> 6, h = z & 63;
    const int m0 = blockIdx.y * 64;
    const float* Ab = d_S + (size_t)z * (CSZ * CSZ);
    const float* Bb = d_xdt + (size_t)(c * CSZ) * INTER_ + h * PP;
    __shared__ float As[16][64], Bs[16][64];
    const int tid = threadIdx.x;
    const int ty = tid >> 4, tx = tid & 15;
    const int lr = tid >> 2, lc = (tid & 3) << 2;
    const int kr = tid >> 4, nc = (tid & 15) << 2;
    float acc[4][4];
#pragma unroll
    for (int i = 0; i < 4; i++)
#pragma unroll
        for (int j = 0; j < 4; j++) acc[i][j] = 0.f;
    for (int k0 = 0; k0 < CSZ; k0 += 16) {
        float4 av = *(const float4*)(Ab + (size_t)(m0 + lr) * CSZ + k0 + lc);
        As[lc + 0][lr] = av.x; As[lc + 1][lr] = av.y; As[lc + 2][lr] = av.z; As[lc + 3][lr] = av.w;
        float4 bv = *(const float4*)(Bb + (size_t)(k0 + kr) * INTER_ + nc);
        *(float4*)&Bs[kr][nc] = bv;
        __syncthreads();
#pragma unroll
        for (int k = 0; k < 16; k++) {
            float a[4], b[4];
            *(float4*)a = *(const float4*)&As[k][ty * 4];
            *(float4*)b = *(const float4*)&Bs[k][tx * 4];
#pragma unroll
            for (int i = 0; i < 4; i++)
#pragma unroll
                for (int j = 0; j < 4; j++) acc[i][j] += a[i] * b[j];
        }
        __syncthreads();
    }
#pragma unroll
    for (int i = 0; i < 4; i++) {
        int l = m0 + ty * 4 + i;
        *(float4*)(d_Y + (size_t)(c * CSZ + l) * INTER_ + h * PP + tx * 4) =
            make_float4(acc[i][0], acc[i][1], acc[i][2], acc[i][3]);
    }
}

__global__ __launch_bounds__(256) void states_kernel() {
    const int z = blockIdx.z;
    const int c = z >> 6, h = z & 63, g = h >> 3;
    const int n0 = blockIdx.x * 64;
    const float* Ab = d_xdtd + (size_t)(h * PP) * LL + c * CSZ;
    const float* Bb = d_conv + (size_t)(c * CSZ) * CONVDIM_ + INTER_ + g * NST;
    __shared__ float As[16][64], Bs[16][64];
    const int tid = threadIdx.x;
    const int ty = tid >> 4, tx = tid & 15;
    const int lr = tid >> 2, lc = (tid & 3) << 2;
    const int kr = tid >> 4, nc = (tid & 15) << 2;
    float acc[4][4];
#pragma unroll
    for (int i = 0; i < 4; i++)
#pragma unroll
        for (int j = 0; j < 4; j++) acc[i][j] = 0.f;
    for (int k0 = 0; k0 < CSZ; k0 += 16) {
        float4 av = *(const float4*)(Ab + (size_t)lr * LL + k0 + lc);
        As[lc + 0][lr] = av.x; As[lc + 1][lr] = av.y; As[lc + 2][lr] = av.z; As[lc + 3][lr] = av.w;
        float4 bv = *(const float4*)(Bb + (size_t)(k0 + kr) * CONVDIM_ + n0 + nc);
        *(float4*)&Bs[kr][nc] = bv;
        __syncthreads();
#pragma unroll
        for (int k = 0; k < 16; k++) {
            float a[4], b[4];
            *(float4*)a = *(const float4*)&As[k][ty * 4];
            *(float4*)b = *(const float4*)&Bs[k][tx * 4];
#pragma unroll
            for (int i = 0; i < 4; i++)
#pragma unroll
                for (int j = 0; j < 4; j++) acc[i][j] += a[i] * b[j];
        }
        __syncthreads();
    }
#pragma unroll
    for (int i = 0; i < 4; i++) {
        int p = ty * 4 + i;
        *(float4*)(d_states + ((size_t)z * PP + p) * NST + n0 + tx * 4) =
            make_float4(acc[i][0], acc[i][1], acc[i][2], acc[i][3]);
    }
}

__global__ void state_scan_kernel() {
    int t = blockIdx.x * blockDim.x + threadIdx.x;
    if (t >= HH * PP * NST) return;
    int n = t & 127, p = (t >> 7) & 63, h = t >> 13;
    float prev = 0.f;
#pragma unroll
    for (int c = 0; c < NCH; c++) {
        size_t idx = ((size_t)(c * HH + h) * PP + p) * NST + n;
        d_prev[idx] = prev;
        float cd = __expf(d_Acs[(size_t)h * LL + c * CSZ + 255]);
        prev = prev * cd + d_states[idx];
    }
}

__global__ __launch_bounds__(256) void yoff_kernel(const float* __restrict__ Dvec) {
    const int z = blockIdx.z;
    const int c = z >> 6, h = z & 63, g = h >> 3;
    const int m0 = blockIdx.y * 64;
    const float* Ab = d_conv + (size_t)(c * CSZ) * CONVDIM_ + (INTER_ + GG * NST) + g * NST;
    const float* Bb = d_prev + (size_t)z * PP * NST;
    __shared__ float As[16][64], Bs[16][64];
    const int tid = threadIdx.x;
    const int ty = tid >> 4, tx = tid & 15;
    const int lr = tid >> 2, lc = (tid & 3) << 2;
    float acc[4][4];
#pragma unroll
    for (int i = 0; i < 4; i++)
#pragma unroll
        for (int j = 0; j < 4; j++) acc[i][j] = 0.f;
    for (int k0 = 0; k0 < NST; k0 += 16) {
        float4 av = *(const float4*)(Ab + (size_t)(m0 + lr) * CONVDIM_ + k0 + lc);
        As[lc + 0][lr] = av.x; As[lc + 1][lr] = av.y; As[lc + 2][lr] = av.z; As[lc + 3][lr] = av.w;
        float4 bv = *(const float4*)(Bb + (size_t)lr * NST + k0 + lc);
        Bs[lc + 0][lr] = bv.x; Bs[lc + 1][lr] = bv.y; Bs[lc + 2][lr] = bv.z; Bs[lc + 3][lr] = bv.w;
        __syncthreads();
#pragma unroll
        for (int k = 0; k < 16; k++) {
            float a[4], b[4];
            *(float4*)a = *(const float4*)&As[k][ty * 4];
            *(float4*)b = *(const float4*)&Bs[k][tx * 4];
#pragma unroll
            for (int i = 0; i < 4; i++)
#pragma unroll
                for (int j = 0; j < 4; j++) acc[i][j] += a[i] * b[j];
        }
        __syncthreads();
    }
    const float* acs = d_Acs + (size_t)h * LL + c * CSZ;
    float Dv = Dvec[h];
#pragma unroll
    for (int i = 0; i < 4; i++) {
        int l = m0 + ty * 4 + i;
        float sd = __expf(acs[l]);
        int gl = c * CSZ + l;
#pragma unroll
        for (int j = 0; j < 4; j++) {
            int p = tx * 4 + j;
            size_t xi = (size_t)gl * CONVDIM_ + h * PP + p;
            size_t yi = (size_t)gl * INTER_ + h * PP + p;
            d_Y[yi] = d_Y[yi] + acc[i][j] * sd + Dv * d_conv[xi];
        }
    }
}

__global__ __launch_bounds__(256) void norm_kernel(const float* __restrict__ norm_weight) {
    __shared__ float gbuf[INTER_];
    __shared__ float rs[GG];
    int l = blockIdx.x, tid = threadIdx.x;
    for (int i = tid; i < INTER_; i += 256) {
        float y = d_Y[(size_t)l * INTER_ + i];
        float gt = d_proj[(size_t)l * PROJ_ + i];
        float sg = 1.f / (1.f + __expf(-gt));
        gbuf[i] = y * gt * sg;
    }
    __syncthreads();
    int w = tid >> 5, lane = tid & 31;
    float ss = 0.f;
    for (int j = lane; j < 512; j += 32) { float v = gbuf[w * 512 + j]; ss += v * v; }
#pragma unroll
    for (int o = 16; o > 0; o >>= 1) ss += __shfl_xor_sync(0xffffffffu, ss, o);
    if (lane == 0) rs[w] = rsqrtf(ss * (1.f / 512.f) + 1e-5f);
    __syncthreads();
    for (int i = tid; i < INTER_; i += 256)
        d_norm[(size_t)l * INTER_ + i] = gbuf[i] * rs[i >> 9] * norm_weight[i];
}

// ============================================================================
extern "C" void kernel_launch(void* const* d_in, const int* in_sizes, int n_in,
                              void* d_out, int out_size) {
    (void)in_sizes; (void)n_in; (void)out_size;
    const float* hidden      = (const float*)d_in[0];
    const float* W_in        = (const float*)d_in[1];
    const float* conv_w      = (const float*)d_in[2];
    const float* conv_b      = (const float*)d_in[3];
    const float* dt_bias     = (const float*)d_in[4];
    const float* A_log       = (const float*)d_in[5];
    const float* Dvec        = (const float*)d_in[6];
    const float* norm_weight = (const float*)d_in[7];
    const float* W_out       = (const float*)d_in[8];
    float* out = (float*)d_out;

    float *p_proj = nullptr, *p_norm = nullptr;
    __nv_bfloat16 *pA1h, *pA1l, *pW1h, *pW1l, *pA2h, *pA2l, *pW2h, *pW2l;
    cudaGetSymbolAddress((void**)&p_proj, d_proj);
    cudaGetSymbolAddress((void**)&p_norm, d_norm);
    cudaGetSymbolAddress((void**)&pA1h, d_A1hi);
    cudaGetSymbolAddress((void**)&pA1l, d_A1lo);
    cudaGetSymbolAddress((void**)&pW1h, d_W1hi);
    cudaGetSymbolAddress((void**)&pW1l, d_W1lo);
    cudaGetSymbolAddress((void**)&pA2h, d_A2hi);
    cudaGetSymbolAddress((void**)&pA2l, d_A2lo);
    cudaGetSymbolAddress((void**)&pW2h, d_W2hi);
    cudaGetSymbolAddress((void**)&pW2l, d_W2lo);

    cudaFuncSetAttribute(gemm_mma, cudaFuncAttributeMaxDynamicSharedMemorySize, MM_SMEM);

    // 0) bf16 hi/lo splits
    {
        int n4 = (LL * DMODEL) / 4;
        cvt_kernel<<<(n4 + 255) / 256, 256>>>(hidden, pA1h, pA1l, n4);
    }
    {
        int n4 = (PROJ_ * DMODEL) / 4;
        cvt_kernel<<<(n4 + 255) / 256, 256>>>(W_in, pW1h, pW1l, n4);
    }
    {
        int n4 = (DMODEL * INTER_) / 4;
        cvt_kernel<<<(n4 + 255) / 256, 256>>>(W_out, pW2h, pW2l, n4);
    }
    // 1) input projection (mma.sync split-bf16)
    {
        dim3 grid(LL / 128, (PROJ_ + 127) / 128);
        gemm_mma<<<grid, 256, MM_SMEM>>>(pA1h, pA1l, pW1h, pW1l, p_proj, LL, PROJ_, DMODEL);
    }
    // 2-3) dt + cumsum
    dt_kernel<<<(LL * HH) / 256, 256>>>(dt_bias);
    acs_kernel<<<(NCH * HH + 255) / 256, 256>>>(A_log);
    // 4) conv + silu
    conv_kernel<<<(LL * CONVDIM_) / 256, 256>>>(conv_w, conv_b);
    // 5-6) xdt, decay-weighted transpose
    xdt_kernel<<<(LL * INTER_) / 256, 256>>>();
    {
        dim3 grid(INTER_ / 32, LL / 32);
        xdtd_kernel<<<grid, dim3(32, 8)>>>();
    }
    // 7-11) chunked SSM
    scores_kernel<<<dim3(4, 4, NBATCH), 256>>>();
    ydiag_kernel<<<dim3(1, 4, NBATCH), 256>>>();
    states_kernel<<<dim3(2, 1, NBATCH), 256>>>();
    state_scan_kernel<<<(HH * PP * NST) / 256, 256>>>();
    yoff_kernel<<<dim3(1, 4, NBATCH), 256>>>(Dvec);
    // 12) gated group RMS norm
    norm_kernel<<<LL, 256>>>(norm_weight);
    // 13) output projection
    {
        int n4 = (LL * INTER_) / 4;
        cvt_kernel<<<(n4 + 255) / 256, 256>>>(p_norm, pA2h, pA2l, n4);
    }
    {
        dim3 grid(LL / 128, DMODEL / 128);
        gemm_mma<<<grid, 256, MM_SMEM>>>(pA2h, pA2l, pW2h, pW2l, out, LL, DMODEL, INTER_);
    }
}

// round 5
// speedup vs baseline: 2.0078x; 1.1241x over previous
#include <cuda_runtime.h>
#include <cuda_bf16.h>
#include <math.h>
#include <stdint.h>

// ---------------- problem constants ----------------
#define HH      64
#define PP      64
#define NST     128
#define GG      8
#define DMODEL  2048
#define CSZ     256
#define LL      4096
#define INTER_  4096
#define CONVDIM_ 6144
#define PROJ_   10304
#define NCH     16
#define NBATCH  1024

// ---------------- fp32 scratch ----------------
__device__ float d_proj[(size_t)LL * PROJ_];
__device__ float d_conv[(size_t)LL * CONVDIM_];
__device__ float d_dt[(size_t)LL * HH];
__device__ float d_Acs[(size_t)HH * LL];
__device__ float d_xdt[(size_t)LL * INTER_];
__device__ float d_states[(size_t)NBATCH * PP * NST];
__device__ float d_prev[(size_t)NBATCH * PP * NST];
__device__ float d_Y[(size_t)LL * INTER_];
__device__ float d_norm[(size_t)LL * INTER_];

// ---------------- bf16 hi/lo operand arrays ----------------
__device__ __nv_bfloat16 d_A1hi[(size_t)LL * DMODEL];
__device__ __nv_bfloat16 d_A1lo[(size_t)LL * DMODEL];
__device__ __nv_bfloat16 d_W1hi[(size_t)PROJ_ * DMODEL];
__device__ __nv_bfloat16 d_W1lo[(size_t)PROJ_ * DMODEL];
__device__ __nv_bfloat16 d_A2hi[(size_t)LL * INTER_];
__device__ __nv_bfloat16 d_A2lo[(size_t)LL * INTER_];
__device__ __nv_bfloat16 d_W2hi[(size_t)DMODEL * INTER_];
__device__ __nv_bfloat16 d_W2lo[(size_t)DMODEL * INTER_];

__device__ __nv_bfloat16 d_Bhi[(size_t)LL * 1024];   // B  [l][g*128+n]
__device__ __nv_bfloat16 d_Blo[(size_t)LL * 1024];
__device__ __nv_bfloat16 d_Chi2[(size_t)LL * 1024];  // C  [l][g*128+n]
__device__ __nv_bfloat16 d_Clo2[(size_t)LL * 1024];
__device__ __nv_bfloat16 d_BThi[(size_t)1024 * LL];  // B^T [g*128+n][l]
__device__ __nv_bfloat16 d_BTlo[(size_t)1024 * LL];
__device__ __nv_bfloat16 d_xThi[(size_t)INTER_ * LL];   // xdt^T   [h*64+p][l]
__device__ __nv_bfloat16 d_xTlo[(size_t)INTER_ * LL];
__device__ __nv_bfloat16 d_xdThi[(size_t)INTER_ * LL];  // (xdt*decay)^T
__device__ __nv_bfloat16 d_xdTlo[(size_t)INTER_ * LL];
__device__ __nv_bfloat16 d_pvhi[(size_t)NBATCH * PP * NST]; // prev [z][p][n]
__device__ __nv_bfloat16 d_pvlo[(size_t)NBATCH * PP * NST];

// ---------------- helpers ----------------
__device__ __forceinline__ uint32_t smem_u32(const void* p) {
    uint32_t a;
    asm("{ .reg .u64 t; cvta.to.shared.u64 t, %1; cvt.u32.u64 %0, t; }" : "=r"(a) : "l"(p));
    return a;
}
__device__ __forceinline__ void cpa16(uint32_t dst, const void* src) {
    asm volatile("cp.async.cg.shared.global [%0], [%1], 16;\n" :: "r"(dst), "l"(src));
}
#define CP_COMMIT() asm volatile("cp.async.commit_group;\n" ::: "memory")
#define CP_WAIT1()  asm volatile("cp.async.wait_group 1;\n" ::: "memory")
#define CP_WAIT0()  asm volatile("cp.async.wait_group 0;\n" ::: "memory")

#define LDSM4(r, addr) \
    asm volatile("ldmatrix.sync.aligned.m8n8.x4.shared.b16 {%0,%1,%2,%3}, [%4];" \
                 : "=r"((r)[0]), "=r"((r)[1]), "=r"((r)[2]), "=r"((r)[3]) : "r"(addr))
#define MMA16816(d, a, b) \
    asm volatile("mma.sync.aligned.m16n8k16.row.col.f32.bf16.bf16.f32 " \
                 "{%0,%1,%2,%3}, {%4,%5,%6,%7}, {%8,%9}, {%0,%1,%2,%3};" \
                 : "+f"((d)[0]), "+f"((d)[1]), "+f"((d)[2]), "+f"((d)[3]) \
                 : "r"((a)[0]), "r"((a)[1]), "r"((a)[2]), "r"((a)[3]), \
                   "r"((b)[0]), "r"((b)[1]))

__device__ __forceinline__ void split2(float v, __nv_bfloat16& h, __nv_bfloat16& l) {
    h = __float2bfloat16_rn(v);
    l = __float2bfloat16_rn(v - __bfloat162float(h));
}

// ============================================================================
// Big split-bf16 GEMM (round-4, validated)
// ============================================================================
#define MM_STAGES 3
#define MM_ROWB   80
#define MM_ABYTES (128 * MM_ROWB)
#define MM_SSTAGE (2 * MM_ABYTES)
#define MM_SMEM   (MM_STAGES * MM_SSTAGE)

__global__ __launch_bounds__(256) void gemm_mma(
    const __nv_bfloat16* __restrict__ Ahi, const __nv_bfloat16* __restrict__ Alo,
    const __nv_bfloat16* __restrict__ Bhi, const __nv_bfloat16* __restrict__ Blo,
    float* __restrict__ C, int M, int N, int K)
{
    extern __shared__ char smem[];
    const int tid  = threadIdx.x;
    const int wid  = tid >> 5;
    const int lane = tid & 31;
    const int m0 = blockIdx.x * 128;
    const int n0 = blockIdx.y * 128;
    const int wm = (wid & 3) * 32;
    const int wn = (wid >> 2) * 64;
    const uint32_t sbase = smem_u32(smem);

    const int KB = K >> 5;
    const int NC = 3 * KB;

    float acc[2][8][4];
#pragma unroll
    for (int i = 0; i < 2; i++)
#pragma unroll
        for (int j = 0; j < 8; j++)
#pragma unroll
            for (int t = 0; t < 4; t++) acc[i][j][t] = 0.f;

    const int it0 = tid, it1 = tid + 256;
    const int ar0 = it0 >> 2, ac0 = (it0 & 3) << 4;
    const int ar1 = it1 >> 2, ac1 = (it1 & 3) << 4;

    auto issue = [&](int j) {
        const int s = j % MM_STAGES;
        const uint32_t As = sbase + s * MM_SSTAGE;
        const uint32_t Bs = As + MM_ABYTES;
        const int seg = j / KB;
        const int kk = j - seg * KB;
        const __nv_bfloat16* Ag = (seg == 1) ? Alo : Ahi;
        const __nv_bfloat16* Bg = (seg == 2) ? Blo : Bhi;
        const size_t kof = (size_t)kk * 32;
        cpa16(As + ar0 * MM_ROWB + ac0, Ag + (size_t)(m0 + ar0) * K + kof + (ac0 >> 1));
        cpa16(As + ar1 * MM_ROWB + ac1, Ag + (size_t)(m0 + ar1) * K + kof + (ac1 >> 1));
        {
            int nn0 = n0 + ar0, nn1 = n0 + ar1;
            int p0 = (nn0 < N) ? 16 : 0;
            int p1 = (nn1 < N) ? 16 : 0;
            if (nn0 >= N) nn0 = 0;
            if (nn1 >= N) nn1 = 0;
            const void* g0 = Bg + (size_t)nn0 * K + kof + (ac0 >> 1);
            const void* g1 = Bg + (size_t)nn1 * K + kof + (ac1 >> 1);
            asm volatile("cp.async.cg.shared.global [%0], [%1], 16, %2;\n"
                         :: "r"(Bs + ar0 * MM_ROWB + ac0), "l"(g0), "r"(p0));
            asm volatile("cp.async.cg.shared.global [%0], [%1], 16, %2;\n"
                         :: "r"(Bs + ar1 * MM_ROWB + ac1), "l"(g1), "r"(p1));
        }
    };

    const int quad = lane >> 3, qj = lane & 7;

    auto compute = [&](int i) {
        const int s = i % MM_STAGES;
        const uint32_t As = sbase + s * MM_SSTAGE;
        const uint32_t Bs = As + MM_ABYTES;
#pragma unroll
        for (int k16 = 0; k16 < 2; k16++) {
            const int k0 = k16 * 16;
            uint32_t a[2][4];
#pragma unroll
            for (int mt = 0; mt < 2; mt++) {
                int row = wm + mt * 16 + ((quad & 1) ? 8 : 0) + qj;
                int kel = k0 + ((quad & 2) ? 8 : 0);
                LDSM4(a[mt], As + row * MM_ROWB + kel * 2);
            }
            uint32_t b[8][2];
#pragma unroll
            for (int np = 0; np < 4; np++) {
                int row = wn + np * 16 + ((quad & 2) ? 8 : 0) + qj;
                int kel = k0 + ((quad & 1) ? 8 : 0);
                uint32_t t[4];
                LDSM4(t, Bs + row * MM_ROWB + kel * 2);
                b[np * 2][0] = t[0]; b[np * 2][1] = t[1];
                b[np * 2 + 1][0] = t[2]; b[np * 2 + 1][1] = t[3];
            }
#pragma unroll
            for (int mt = 0; mt < 2; mt++)
#pragma unroll
                for (int nt = 0; nt < 8; nt++) MMA16816(acc[mt][nt], a[mt], b[nt]);
        }
    };

    issue(0); CP_COMMIT();
    issue(1); CP_COMMIT();
    for (int i = 0; i < NC; i++) {
        if (i + 2 < NC) issue(i + 2);
        CP_COMMIT();
        asm volatile("cp.async.wait_group 2;\n" ::: "memory");
        __syncthreads();
        compute(i);
        __syncthreads();
    }

    const int g = lane >> 2, t4 = lane & 3;
#pragma unroll
    for (int mt = 0; mt < 2; mt++)
#pragma unroll
        for (int nt = 0; nt < 8; nt++) {
            int m = m0 + wm + mt * 16 + g;
            int n = n0 + wn + nt * 8 + t4 * 2;
            if (n < N) {
                *(float2*)(C + (size_t)m * N + n) = make_float2(acc[mt][nt][0], acc[mt][nt][1]);
                *(float2*)(C + (size_t)(m + 8) * N + n) = make_float2(acc[mt][nt][2], acc[mt][nt][3]);
            }
        }
}

// ============================================================================
// fp32 -> bf16 hi/lo split
// ============================================================================
__global__ void cvt_kernel(const float* __restrict__ src, __nv_bfloat16* __restrict__ hi,
                           __nv_bfloat16* __restrict__ lo, int n4) {
    int i = blockIdx.x * blockDim.x + threadIdx.x;
    if (i >= n4) return;
    float4 v = ((const float4*)src)[i];
    __nv_bfloat16 h0, h1, h2, h3, l0, l1, l2, l3;
    split2(v.x, h0, l0); split2(v.y, h1, l1);
    split2(v.z, h2, l2); split2(v.w, h3, l3);
    ((__nv_bfloat162*)hi)[2 * i]     = __nv_bfloat162(h0, h1);
    ((__nv_bfloat162*)hi)[2 * i + 1] = __nv_bfloat162(h2, h3);
    ((__nv_bfloat162*)lo)[2 * i]     = __nv_bfloat162(l0, l1);
    ((__nv_bfloat162*)lo)[2 * i + 1] = __nv_bfloat162(l2, l3);
}

// ============================================================================
// elementwise / scan kernels
// ============================================================================
__global__ void dt_kernel(const float* __restrict__ dt_bias) {
    int id = blockIdx.x * blockDim.x + threadIdx.x;
    if (id >= LL * HH) return;
    int l = id >> 6, h = id & 63;
    float v = d_proj[(size_t)l * PROJ_ + INTER_ + CONVDIM_ + h] + dt_bias[h];
    float sp = (v > 20.f) ? v : log1pf(expf(v));
    d_dt[id] = sp;
}

__global__ void acs_kernel(const float* __restrict__ A_log) {
    int t = blockIdx.x * blockDim.x + threadIdx.x;
    if (t >= NCH * HH) return;
    int h = t & 63, c = t >> 6;
    float Ah = -expf(A_log[h]);
    float run = 0.f;
    for (int s = 0; s < CSZ; s++) {
        run += d_dt[(size_t)(c * CSZ + s) * HH + h] * Ah;
        d_Acs[(size_t)h * LL + c * CSZ + s] = run;
    }
}

__global__ void conv_kernel(const float* __restrict__ conv_w, const float* __restrict__ conv_b) {
    int id = blockIdx.x * blockDim.x + threadIdx.x;
    if (id >= LL * CONVDIM_) return;
    int l = id / CONVDIM_, cc = id % CONVDIM_;
    float acc = conv_b[cc];
#pragma unroll
    for (int k = 0; k < 4; k++) {
        int li = l - 3 + k;
        if (li >= 0) acc += conv_w[cc * 4 + k] * d_proj[(size_t)li * PROJ_ + INTER_ + cc];
    }
    d_conv[id] = acc / (1.f + __expf(-acc));
}

__global__ void xdt_kernel() {
    int id = blockIdx.x * blockDim.x + threadIdx.x;
    if (id >= LL * INTER_) return;
    int l = id >> 12, hp = id & 4095, h = hp >> 6;
    d_xdt[id] = d_conv[(size_t)l * CONVDIM_ + hp] * d_dt[(size_t)l * HH + h];
}

// B/C row-major hi/lo splits from conv output
__global__ void cvt_bc_kernel() {
    int id = blockIdx.x * blockDim.x + threadIdx.x;
    if (id >= LL * 2048) return;
    int l = id >> 11, j = id & 2047;
    float v = d_conv[(size_t)l * CONVDIM_ + INTER_ + j];
    __nv_bfloat16 h, lo;
    split2(v, h, lo);
    if (j < 1024) { d_Bhi[(size_t)l * 1024 + j] = h; d_Blo[(size_t)l * 1024 + j] = lo; }
    else { d_Chi2[(size_t)l * 1024 + j - 1024] = h; d_Clo2[(size_t)l * 1024 + j - 1024] = lo; }
}

// B^T hi/lo [g*128+n][l]
__global__ void btrans_kernel() {
    __shared__ float tile[32][33];
    int x = blockIdx.x * 32 + threadIdx.x;   // gn
    int y0 = blockIdx.y * 32;                // l
    for (int j = threadIdx.y; j < 32; j += 8)
        tile[j][threadIdx.x] = d_conv[(size_t)(y0 + j) * CONVDIM_ + INTER_ + x];
    __syncthreads();
    int l = y0 + threadIdx.x;
    for (int j = threadIdx.y; j < 32; j += 8) {
        int gn = blockIdx.x * 32 + j;
        __nv_bfloat16 h, lo;
        split2(tile[threadIdx.x][j], h, lo);
        d_BThi[(size_t)gn * LL + l] = h;
        d_BTlo[(size_t)gn * LL + l] = lo;
    }
}

// xdt^T hi/lo and (xdt*decay)^T hi/lo, [h*64+p][l]
__global__ void xtrans_kernel() {
    __shared__ float tile[32][33];
    int x = blockIdx.x * 32 + threadIdx.x;   // hp
    int y0 = blockIdx.y * 32;                // l
    for (int j = threadIdx.y; j < 32; j += 8)
        tile[j][threadIdx.x] = d_xdt[(size_t)(y0 + j) * INTER_ + x];
    __syncthreads();
    int l = y0 + threadIdx.x;
    int lastl = l | (CSZ - 1);
    for (int j = threadIdx.y; j < 32; j += 8) {
        int hp = blockIdx.x * 32 + j;
        int h = hp >> 6;
        float v = tile[threadIdx.x][j];
        __nv_bfloat16 hh, ll;
        split2(v, hh, ll);
        d_xThi[(size_t)hp * LL + l] = hh;
        d_xTlo[(size_t)hp * LL + l] = ll;
        float dec = __expf(d_Acs[(size_t)h * LL + lastl] - d_Acs[(size_t)h * LL + l]);
        split2(v * dec, hh, ll);
        d_xdThi[(size_t)hp * LL + l] = hh;
        d_xdTlo[(size_t)hp * LL + l] = ll;
    }
}

__global__ void cvt_prev_kernel() {
    int id = blockIdx.x * blockDim.x + threadIdx.x;
    if (id >= NBATCH * PP * NST) return;
    __nv_bfloat16 h, l;
    split2(d_prev[id], h, l);
    d_pvhi[id] = h;
    d_pvlo[id] = l;
}

__global__ void state_scan_kernel() {
    int t = blockIdx.x * blockDim.x + threadIdx.x;
    if (t >= HH * PP * NST) return;
    int n = t & 127, p = (t >> 7) & 63, h = t >> 13;
    float prev = 0.f;
#pragma unroll
    for (int c = 0; c < NCH; c++) {
        size_t idx = ((size_t)(c * HH + h) * PP + p) * NST + n;
        d_prev[idx] = prev;
        float cd = __expf(d_Acs[(size_t)h * LL + c * CSZ + 255]);
        prev = prev * cd + d_states[idx];
    }
}

// ============================================================================
// Fused scores + Y_diag kernel (tensor cores, split-bf16 both stages)
// grid (2, NBATCH): blockIdx.x = l-half, blockIdx.y = z = c*64+h
// ============================================================================
#define CK_ROWB 80
#define CK_STAGE (4 * 128 * CK_ROWB)      // 40960: Chi,Clo,Bhi,Blo chunks
#define CK_SROW 272
#define CK_SOFF (2 * CK_STAGE)            // 81920
#define CK_SBYT (128 * CK_SROW)           // 34816
#define CK_XOFF (CK_SOFF + 2 * CK_SBYT)   // 151552
#define CK_XBYT (64 * CK_SROW)            // 17408
#define CK_SMEM (CK_XOFF + 2 * CK_XBYT)   // 186368

__global__ __launch_bounds__(256) void chunk_kernel() {
    const int lhalf = blockIdx.x;
    const int z = blockIdx.y;
    const int c = z >> 6, h = z & 63, g = h >> 3;
    extern __shared__ char sm[];
    const uint32_t sb = smem_u32(sm);
    const int tid = threadIdx.x;
    const int wid = tid >> 5, lane = tid & 31;
    const int quad = lane >> 3, qj = lane & 7;
    const int wy = wid & 3, wx = wid >> 2;     // 4 x 2 warps
    const int l0 = c * CSZ + lhalf * 128;

    float yacc[2][4][4];
#pragma unroll
    for (int i = 0; i < 2; i++)
#pragma unroll
        for (int j = 0; j < 4; j++)
#pragma unroll
            for (int t = 0; t < 4; t++) yacc[i][j][t] = 0.f;

    const float* acsH = d_Acs + (size_t)h * LL + c * CSZ;

    for (int sh = 0; sh <= lhalf; sh++) {
        const int s0 = c * CSZ + sh * 128;
        float acc[2][8][4];
#pragma unroll
        for (int i = 0; i < 2; i++)
#pragma unroll
            for (int j = 0; j < 8; j++)
#pragma unroll
                for (int t = 0; t < 4; t++) acc[i][j][t] = 0.f;

        // ---- issue X (xdt^T tile: 64 p-rows x 128 s-cols, hi/lo) + chunk 0, then chunk 1
#pragma unroll
        for (int rep = 0; rep < 4; rep++) {
            int slot = tid + rep * 256;
            int row = slot >> 4, c16 = (slot & 15) * 16;
            size_t off = (size_t)(h * 64 + row) * LL + s0 + (c16 >> 1);
            cpa16(sb + CK_XOFF + row * CK_SROW + c16, d_xThi + off);
            cpa16(sb + CK_XOFF + CK_XBYT + row * CK_SROW + c16, d_xTlo + off);
        }
        {
            // chunk 0
            const uint32_t base = sb + 0 * CK_STAGE;
#pragma unroll
            for (int rep = 0; rep < 2; rep++) {
                int slot = tid + rep * 256;
                int row = slot >> 2, c16 = (slot & 3) * 16;
                int kofe = 0 * 32 + (c16 >> 1);
                size_t crow = (size_t)(l0 + row) * 1024 + g * 128 + kofe;
                size_t brow = (size_t)(s0 + row) * 1024 + g * 128 + kofe;
                cpa16(base + row * CK_ROWB + c16, d_Chi2 + crow);
                cpa16(base + 10240 + row * CK_ROWB + c16, d_Clo2 + crow);
                cpa16(base + 20480 + row * CK_ROWB + c16, d_Bhi + brow);
                cpa16(base + 30720 + row * CK_ROWB + c16, d_Blo + brow);
            }
        }
        CP_COMMIT();
        {
            const uint32_t base = sb + 1 * CK_STAGE;
#pragma unroll
            for (int rep = 0; rep < 2; rep++) {
                int slot = tid + rep * 256;
                int row = slot >> 2, c16 = (slot & 3) * 16;
                int kofe = 1 * 32 + (c16 >> 1);
                size_t crow = (size_t)(l0 + row) * 1024 + g * 128 + kofe;
                size_t brow = (size_t)(s0 + row) * 1024 + g * 128 + kofe;
                cpa16(base + row * CK_ROWB + c16, d_Chi2 + crow);
                cpa16(base + 10240 + row * CK_ROWB + c16, d_Clo2 + crow);
                cpa16(base + 20480 + row * CK_ROWB + c16, d_Bhi + brow);
                cpa16(base + 30720 + row * CK_ROWB + c16, d_Blo + brow);
            }
        }
        CP_COMMIT();

        // ---- phase A: S = C·B^T (3-term), K = 128 in 4 chunks of 32
        for (int kc = 0; kc < 4; kc++) {
            if (kc == 3) CP_WAIT0(); else CP_WAIT1();
            __syncthreads();
            {
                const uint32_t base = sb + (kc & 1) * CK_STAGE;
                const uint32_t Ch = base, Cl = base + 10240, Bh = base + 20480, Bl = base + 30720;
#pragma unroll
                for (int k16 = 0; k16 < 2; k16++) {
                    const int k0 = k16 * 16;
                    uint32_t ah[2][4], al_[2][4];
#pragma unroll
                    for (int mt = 0; mt < 2; mt++) {
                        int row = wy * 32 + mt * 16 + ((quad & 1) ? 8 : 0) + qj;
                        int kel = k0 + ((quad & 2) ? 8 : 0);
                        LDSM4(ah[mt], Ch + row * CK_ROWB + kel * 2);
                        LDSM4(al_[mt], Cl + row * CK_ROWB + kel * 2);
                    }
                    uint32_t bh[8][2], bl[8][2];
#pragma unroll
                    for (int np = 0; np < 4; np++) {
                        int row = wx * 64 + np * 16 + ((quad & 2) ? 8 : 0) + qj;
                        int kel = k0 + ((quad & 1) ? 8 : 0);
                        uint32_t t[4];
                        LDSM4(t, Bh + row * CK_ROWB + kel * 2);
                        bh[np * 2][0] = t[0]; bh[np * 2][1] = t[1];
                        bh[np * 2 + 1][0] = t[2]; bh[np * 2 + 1][1] = t[3];
                        LDSM4(t, Bl + row * CK_ROWB + kel * 2);
                        bl[np * 2][0] = t[0]; bl[np * 2][1] = t[1];
                        bl[np * 2 + 1][0] = t[2]; bl[np * 2 + 1][1] = t[3];
                    }
#pragma unroll
                    for (int mt = 0; mt < 2; mt++)
#pragma unroll
                        for (int nt = 0; nt < 8; nt++) {
                            MMA16816(acc[mt][nt], ah[mt], bh[nt]);
                            MMA16816(acc[mt][nt], al_[mt], bh[nt]);
                            MMA16816(acc[mt][nt], ah[mt], bl[nt]);
                        }
                }
            }
            __syncthreads();
            if (kc + 2 < 4) {
                const uint32_t base = sb + ((kc + 2) & 1) * CK_STAGE;
#pragma unroll
                for (int rep = 0; rep < 2; rep++) {
                    int slot = tid + rep * 256;
                    int row = slot >> 2, c16 = (slot & 3) * 16;
                    int kofe = (kc + 2) * 32 + (c16 >> 1);
                    size_t crow = (size_t)(l0 + row) * 1024 + g * 128 + kofe;
                    size_t brow = (size_t)(s0 + row) * 1024 + g * 128 + kofe;
                    cpa16(base + row * CK_ROWB + c16, d_Chi2 + crow);
                    cpa16(base + 10240 + row * CK_ROWB + c16, d_Clo2 + crow);
                    cpa16(base + 20480 + row * CK_ROWB + c16, d_Bhi + brow);
                    cpa16(base + 30720 + row * CK_ROWB + c16, d_Blo + brow);
                }
                CP_COMMIT();
            }
        }

        // ---- decay + causal mask, split S into smem bf16 hi/lo
        {
            const bool diag = (sh == lhalf);
            char* Sh = sm + CK_SOFF;
            char* Sl = sm + CK_SOFF + CK_SBYT;
#pragma unroll
            for (int mt = 0; mt < 2; mt++) {
                int r0 = wy * 32 + mt * 16 + (lane >> 2);
#pragma unroll
                for (int half = 0; half < 2; half++) {
                    int r = r0 + half * 8;
                    float al = acsH[lhalf * 128 + r];
#pragma unroll
                    for (int nt = 0; nt < 8; nt++) {
                        int cc = wx * 64 + nt * 8 + (lane & 3) * 2;
                        float v0 = acc[mt][nt][half * 2 + 0];
                        float v1 = acc[mt][nt][half * 2 + 1];
                        float as0 = acsH[sh * 128 + cc];
                        float as1 = acsH[sh * 128 + cc + 1];
                        v0 = (!diag || (cc <= r)) ? v0 * __expf(al - as0) : 0.f;
                        v1 = (!diag || (cc + 1 <= r)) ? v1 * __expf(al - as1) : 0.f;
                        __nv_bfloat16 h0, h1, q0, q1;
                        split2(v0, h0, q0);
                        split2(v1, h1, q1);
                        *(__nv_bfloat162*)(Sh + r * CK_SROW + cc * 2) = __nv_bfloat162(h0, h1);
                        *(__nv_bfloat162*)(Sl + r * CK_SROW + cc * 2) = __nv_bfloat162(q0, q1);
                    }
                }
            }
        }
        __syncthreads();

        // ---- phase B: Y_diag += S·xdt (3-term), K = 128 (s)
        {
            const uint32_t Sh = sb + CK_SOFF, Sl = sb + CK_SOFF + CK_SBYT;
            const uint32_t Xh = sb + CK_XOFF, Xl = sb + CK_XOFF + CK_XBYT;
#pragma unroll 2
            for (int k16 = 0; k16 < 8; k16++) {
                const int k0 = k16 * 16;
                uint32_t ah[2][4], al_[2][4];
#pragma unroll
                for (int mt = 0; mt < 2; mt++) {
                    int row = wy * 32 + mt * 16 + ((quad & 1) ? 8 : 0) + qj;
                    int kel = k0 + ((quad & 2) ? 8 : 0);
                    LDSM4(ah[mt], Sh + row * CK_SROW + kel * 2);
                    LDSM4(al_[mt], Sl + row * CK_SROW + kel * 2);
                }
                uint32_t bh[4][2], bl[4][2];
#pragma unroll
                for (int np = 0; np < 2; np++) {
                    int row = wx * 32 + np * 16 + ((quad & 2) ? 8 : 0) + qj;
                    int kel = k0 + ((quad & 1) ? 8 : 0);
                    uint32_t t[4];
                    LDSM4(t, Xh + row * CK_SROW + kel * 2);
                    bh[np * 2][0] = t[0]; bh[np * 2][1] = t[1];
                    bh[np * 2 + 1][0] = t[2]; bh[np * 2 + 1][1] = t[3];
                    LDSM4(t, Xl + row * CK_SROW + kel * 2);
                    bl[np * 2][0] = t[0]; bl[np * 2][1] = t[1];
                    bl[np * 2 + 1][0] = t[2]; bl[np * 2 + 1][1] = t[3];
                }
#pragma unroll
                for (int mt = 0; mt < 2; mt++)
#pragma unroll
                    for (int nt = 0; nt < 4; nt++) {
                        MMA16816(yacc[mt][nt], ah[mt], bh[nt]);
                        MMA16816(yacc[mt][nt], al_[mt], bh[nt]);
                        MMA16816(yacc[mt][nt], ah[mt], bl[nt]);
                    }
            }
        }
        __syncthreads();
    }

    // ---- epilogue: write Y_diag
#pragma unroll
    for (int mt = 0; mt < 2; mt++)
#pragma unroll
        for (int nt = 0; nt < 4; nt++) {
            int r = wy * 32 + mt * 16 + (lane >> 2);
            int gl = l0 + r;
            int p = wx * 32 + nt * 8 + (lane & 3) * 2;
            *(float2*)(d_Y + (size_t)gl * INTER_ + h * 64 + p) =
                make_float2(yacc[mt][nt][0], yacc[mt][nt][1]);
            *(float2*)(d_Y + (size_t)(gl + 8) * INTER_ + h * 64 + p) =
                make_float2(yacc[mt][nt][2], yacc[mt][nt][3]);
        }
}

// ============================================================================
// states kernel: states[p,n] = sum_s xdtd^T[p,s]·B^T[n,s]   (3-term mma)
// grid NBATCH; M=64, N=128, K=256 in 8 chunks of 32
// ============================================================================
#define ST_STRIDE 30720
#define ST_SMEM   (2 * ST_STRIDE)

__global__ __launch_bounds__(256) void states_mma_kernel() {
    const int z = blockIdx.x;
    const int c = z >> 6, h = z & 63, g = h >> 3;
    extern __shared__ char sm[];
    const uint32_t sb = smem_u32(sm);
    const int tid = threadIdx.x;
    const int wid = tid >> 5, lane = tid & 31;
    const int quad = lane >> 3, qj = lane & 7;
    const int wy = wid & 1, wx = wid >> 1;   // 2 x 4 warps (M=64, N=128)

    float acc[2][4][4];
#pragma unroll
    for (int i = 0; i < 2; i++)
#pragma unroll
        for (int j = 0; j < 4; j++)
#pragma unroll
            for (int t = 0; t < 4; t++) acc[i][j][t] = 0.f;

    auto issue = [&](int kc) {
        const uint32_t base = sb + (kc & 1) * ST_STRIDE;
        {
            int slot = tid;
            int row = slot >> 2, c16 = (slot & 3) * 16;
            size_t off = (size_t)(h * 64 + row) * LL + c * CSZ + kc * 32 + (c16 >> 1);
            cpa16(base + row * 80 + c16, d_xdThi + off);
            cpa16(base + 5120 + row * 80 + c16, d_xdTlo + off);
        }
#pragma unroll
        for (int rep = 0; rep < 2; rep++) {
            int slot = tid + rep * 256;
            int row = slot >> 2, c16 = (slot & 3) * 16;
            size_t off = (size_t)(g * 128 + row) * LL + c * CSZ + kc * 32 + (c16 >> 1);
            cpa16(base + 10240 + row * 80 + c16, d_BThi + off);
            cpa16(base + 20480 + row * 80 + c16, d_BTlo + off);
        }
    };

    issue(0); CP_COMMIT();
    issue(1); CP_COMMIT();
    for (int kc = 0; kc < 8; kc++) {
        if (kc == 7) CP_WAIT0(); else CP_WAIT1();
        __syncthreads();
        {
            const uint32_t base = sb + (kc & 1) * ST_STRIDE;
            const uint32_t Ah = base, Al = base + 5120, Bh = base + 10240, Bl = base + 20480;
#pragma unroll
            for (int k16 = 0; k16 < 2; k16++) {
                const int k0 = k16 * 16;
                uint32_t ah[2][4], al_[2][4];
#pragma unroll
                for (int mt = 0; mt < 2; mt++) {
                    int row = wy * 32 + mt * 16 + ((quad & 1) ? 8 : 0) + qj;
                    int kel = k0 + ((quad & 2) ? 8 : 0);
                    LDSM4(ah[mt], Ah + row * 80 + kel * 2);
                    LDSM4(al_[mt], Al + row * 80 + kel * 2);
                }
                uint32_t bh[4][2], bl[4][2];
#pragma unroll
                for (int np = 0; np < 2; np++) {
                    int row = wx * 32 + np * 16 + ((quad & 2) ? 8 : 0) + qj;
                    int kel = k0 + ((quad & 1) ? 8 : 0);
                    uint32_t t[4];
                    LDSM4(t, Bh + row * 80 + kel * 2);
                    bh[np * 2][0] = t[0]; bh[np * 2][1] = t[1];
                    bh[np * 2 + 1][0] = t[2]; bh[np * 2 + 1][1] = t[3];
                    LDSM4(t, Bl + row * 80 + kel * 2);
                    bl[np * 2][0] = t[0]; bl[np * 2][1] = t[1];
                    bl[np * 2 + 1][0] = t[2]; bl[np * 2 + 1][1] = t[3];
                }
#pragma unroll
                for (int mt = 0; mt < 2; mt++)
#pragma unroll
                    for (int nt = 0; nt < 4; nt++) {
                        MMA16816(acc[mt][nt], ah[mt], bh[nt]);
                        MMA16816(acc[mt][nt], al_[mt], bh[nt]);
                        MMA16816(acc[mt][nt], ah[mt], bl[nt]);
                    }
            }
        }
        __syncthreads();
        if (kc + 2 < 8) { issue(kc + 2); CP_COMMIT(); }
    }

#pragma unroll
    for (int mt = 0; mt < 2; mt++)
#pragma unroll
        for (int nt = 0; nt < 4; nt++) {
            int p = wy * 32 + mt * 16 + (lane >> 2);
            int n = wx * 32 + nt * 8 + (lane & 3) * 2;
            *(float2*)(d_states + (size_t)z * 8192 + p * 128 + n) =
                make_float2(acc[mt][nt][0], acc[mt][nt][1]);
            *(float2*)(d_states + (size_t)z * 8192 + (p + 8) * 128 + n) =
                make_float2(acc[mt][nt][2], acc[mt][nt][3]);
        }
}

// ============================================================================
// yoff kernel: Y[l,p] += exp(Acs[l]) * sum_n C[l,n]·prev[p,n] + D[h]*x[l,p]
// grid (2, NBATCH); M=128, N=64, K=128 in 4 chunks of 32
// ============================================================================
__global__ __launch_bounds__(256) void yoff_mma_kernel(const float* __restrict__ Dvec) {
    const int lhalf = blockIdx.x;
    const int z = blockIdx.y;
    const int c = z >> 6, h = z & 63, g = h >> 3;
    extern __shared__ char sm[];
    const uint32_t sb = smem_u32(sm);
    const int tid = threadIdx.x;
    const int wid = tid >> 5, lane = tid & 31;
    const int quad = lane >> 3, qj = lane & 7;
    const int wy = wid & 3, wx = wid >> 2;   // 4 x 2 (M=128, N=64)
    const int l0 = c * CSZ + lhalf * 128;

    float acc[2][4][4];
#pragma unroll
    for (int i = 0; i < 2; i++)
#pragma unroll
        for (int j = 0; j < 4; j++)
#pragma unroll
            for (int t = 0; t < 4; t++) acc[i][j][t] = 0.f;

    auto issue = [&](int kc) {
        const uint32_t base = sb + (kc & 1) * ST_STRIDE;
#pragma unroll
        for (int rep = 0; rep < 2; rep++) {
            int slot = tid + rep * 256;
            int row = slot >> 2, c16 = (slot & 3) * 16;
            size_t off = (size_t)(l0 + row) * 1024 + g * 128 + kc * 32 + (c16 >> 1);
            cpa16(base + row * 80 + c16, d_Chi2 + off);
            cpa16(base + 10240 + row * 80 + c16, d_Clo2 + off);
        }
        {
            int slot = tid;
            int row = slot >> 2, c16 = (slot & 3) * 16;
            size_t off = (size_t)z * 8192 + row * 128 + kc * 32 + (c16 >> 1);
            cpa16(base + 20480 + row * 80 + c16, d_pvhi + off);
            cpa16(base + 25600 + row * 80 + c16, d_pvlo + off);
        }
    };

    issue(0); CP_COMMIT();
    issue(1); CP_COMMIT();
    for (int kc = 0; kc < 4; kc++) {
        if (kc == 3) CP_WAIT0(); else CP_WAIT1();
        __syncthreads();
        {
            const uint32_t base = sb + (kc & 1) * ST_STRIDE;
            const uint32_t Ah = base, Al = base + 10240, Bh = base + 20480, Bl = base + 25600;
#pragma unroll
            for (int k16 = 0; k16 < 2; k16++) {
                const int k0 = k16 * 16;
                uint32_t ah[2][4], al_[2][4];
#pragma unroll
                for (int mt = 0; mt < 2; mt++) {
                    int row = wy * 32 + mt * 16 + ((quad & 1) ? 8 : 0) + qj;
                    int kel = k0 + ((quad & 2) ? 8 : 0);
                    LDSM4(ah[mt], Ah + row * 80 + kel * 2);
                    LDSM4(al_[mt], Al + row * 80 + kel * 2);
                }
                uint32_t bh[4][2], bl[4][2];
#pragma unroll
                for (int np = 0; np < 2; np++) {
                    int row = wx * 32 + np * 16 + ((quad & 2) ? 8 : 0) + qj;
                    int kel = k0 + ((quad & 1) ? 8 : 0);
                    uint32_t t[4];
                    LDSM4(t, Bh + row * 80 + kel * 2);
                    bh[np * 2][0] = t[0]; bh[np * 2][1] = t[1];
                    bh[np * 2 + 1][0] = t[2]; bh[np * 2 + 1][1] = t[3];
                    LDSM4(t, Bl + row * 80 + kel * 2);
                    bl[np * 2][0] = t[0]; bl[np * 2][1] = t[1];
                    bl[np * 2 + 1][0] = t[2]; bl[np * 2 + 1][1] = t[3];
                }
#pragma unroll
                for (int mt = 0; mt < 2; mt++)
#pragma unroll
                    for (int nt = 0; nt < 4; nt++) {
                        MMA16816(acc[mt][nt], ah[mt], bh[nt]);
                        MMA16816(acc[mt][nt], al_[mt], bh[nt]);
                        MMA16816(acc[mt][nt], ah[mt], bl[nt]);
                    }
            }
        }
        __syncthreads();
        if (kc + 2 < 4) { issue(kc + 2); CP_COMMIT(); }
    }

    const float Dv = Dvec[h];
    const float* acsH = d_Acs + (size_t)h * LL;
#pragma unroll
    for (int mt = 0; mt < 2; mt++)
#pragma unroll
        for (int nt = 0; nt < 4; nt++) {
            int r = wy * 32 + mt * 16 + (lane >> 2);
            int p = wx * 32 + nt * 8 + (lane & 3) * 2;
#pragma unroll
            for (int half = 0; half < 2; half++) {
                int gl = l0 + r + half * 8;
                float sd = __expf(acsH[gl]);
                float2 y = *(float2*)(d_Y + (size_t)gl * INTER_ + h * 64 + p);
                float2 x = *(float2*)(d_conv + (size_t)gl * CONVDIM_ + h * 64 + p);
                y.x += acc[mt][nt][half * 2 + 0] * sd + Dv * x.x;
                y.y += acc[mt][nt][half * 2 + 1] * sd + Dv * x.y;
                *(float2*)(d_Y + (size_t)gl * INTER_ + h * 64 + p) = y;
            }
        }
}

// ============================================================================
// gated group RMS norm
// ============================================================================
__global__ __launch_bounds__(256) void norm_kernel(const float* __restrict__ norm_weight) {
    __shared__ float gbuf[INTER_];
    __shared__ float rs[GG];
    int l = blockIdx.x, tid = threadIdx.x;
    for (int i = tid; i < INTER_; i += 256) {
        float y = d_Y[(size_t)l * INTER_ + i];
        float gt = d_proj[(size_t)l * PROJ_ + i];
        float sg = 1.f / (1.f + __expf(-gt));
        gbuf[i] = y * gt * sg;
    }
    __syncthreads();
    int w = tid >> 5, lane = tid & 31;
    float ss = 0.f;
    for (int j = lane; j < 512; j += 32) { float v = gbuf[w * 512 + j]; ss += v * v; }
#pragma unroll
    for (int o = 16; o > 0; o >>= 1) ss += __shfl_xor_sync(0xffffffffu, ss, o);
    if (lane == 0) rs[w] = rsqrtf(ss * (1.f / 512.f) + 1e-5f);
    __syncthreads();
    for (int i = tid; i < INTER_; i += 256)
        d_norm[(size_t)l * INTER_ + i] = gbuf[i] * rs[i >> 9] * norm_weight[i];
}

// ============================================================================
extern "C" void kernel_launch(void* const* d_in, const int* in_sizes, int n_in,
                              void* d_out, int out_size) {
    (void)in_sizes; (void)n_in; (void)out_size;
    const float* hidden      = (const float*)d_in[0];
    const float* W_in        = (const float*)d_in[1];
    const float* conv_w      = (const float*)d_in[2];
    const float* conv_b      = (const float*)d_in[3];
    const float* dt_bias     = (const float*)d_in[4];
    const float* A_log       = (const float*)d_in[5];
    const float* Dvec        = (const float*)d_in[6];
    const float* norm_weight = (const float*)d_in[7];
    const float* W_out       = (const float*)d_in[8];
    float* out = (float*)d_out;

    float *p_proj = nullptr, *p_norm = nullptr;
    __nv_bfloat16 *pA1h, *pA1l, *pW1h, *pW1l, *pA2h, *pA2l, *pW2h, *pW2l;
    cudaGetSymbolAddress((void**)&p_proj, d_proj);
    cudaGetSymbolAddress((void**)&p_norm, d_norm);
    cudaGetSymbolAddress((void**)&pA1h, d_A1hi);
    cudaGetSymbolAddress((void**)&pA1l, d_A1lo);
    cudaGetSymbolAddress((void**)&pW1h, d_W1hi);
    cudaGetSymbolAddress((void**)&pW1l, d_W1lo);
    cudaGetSymbolAddress((void**)&pA2h, d_A2hi);
    cudaGetSymbolAddress((void**)&pA2l, d_A2lo);
    cudaGetSymbolAddress((void**)&pW2h, d_W2hi);
    cudaGetSymbolAddress((void**)&pW2l, d_W2lo);

    cudaFuncSetAttribute(gemm_mma, cudaFuncAttributeMaxDynamicSharedMemorySize, MM_SMEM);
    cudaFuncSetAttribute(chunk_kernel, cudaFuncAttributeMaxDynamicSharedMemorySize, CK_SMEM);
    cudaFuncSetAttribute(states_mma_kernel, cudaFuncAttributeMaxDynamicSharedMemorySize, ST_SMEM);
    cudaFuncSetAttribute(yoff_mma_kernel, cudaFuncAttributeMaxDynamicSharedMemorySize, ST_SMEM);

    // 0) splits for big GEMM operands
    { int n4 = (LL * DMODEL) / 4;    cvt_kernel<<<(n4 + 255) / 256, 256>>>(hidden, pA1h, pA1l, n4); }
    { int n4 = (PROJ_ * DMODEL) / 4; cvt_kernel<<<(n4 + 255) / 256, 256>>>(W_in, pW1h, pW1l, n4); }
    { int n4 = (DMODEL * INTER_) / 4; cvt_kernel<<<(n4 + 255) / 256, 256>>>(W_out, pW2h, pW2l, n4); }
    // 1) input projection
    {
        dim3 grid(LL / 128, (PROJ_ + 127) / 128);
        gemm_mma<<<grid, 256, MM_SMEM>>>(pA1h, pA1l, pW1h, pW1l, p_proj, LL, PROJ_, DMODEL);
    }
    // 2-4) dt, cumsum, conv
    dt_kernel<<<(LL * HH) / 256, 256>>>(dt_bias);
    acs_kernel<<<(NCH * HH + 255) / 256, 256>>>(A_log);
    conv_kernel<<<(LL * CONVDIM_) / 256, 256>>>(conv_w, conv_b);
    // 5) operand prep
    xdt_kernel<<<(LL * INTER_) / 256, 256>>>();
    cvt_bc_kernel<<<(LL * 2048) / 256, 256>>>();
    { dim3 grid(1024 / 32, LL / 32); btrans_kernel<<<grid, dim3(32, 8)>>>(); }
    { dim3 grid(INTER_ / 32, LL / 32); xtrans_kernel<<<grid, dim3(32, 8)>>>(); }
    // 6) fused scores + Y_diag
    chunk_kernel<<<dim3(2, NBATCH), 256, CK_SMEM>>>();
    // 7) states, scan, prev split
    states_mma_kernel<<<NBATCH, 256, ST_SMEM>>>();
    state_scan_kernel<<<(HH * PP * NST) / 256, 256>>>();
    cvt_prev_kernel<<<(NBATCH * PP * NST) / 256, 256>>>();
    // 8) Y_off + combine
    yoff_mma_kernel<<<dim3(2, NBATCH), 256, ST_SMEM>>>(Dvec);
    // 9) norm
    norm_kernel<<<LL, 256>>>(norm_weight);
    // 10) output projection
    { int n4 = (LL * INTER_) / 4; cvt_kernel<<<(n4 + 255) / 256, 256>>>(p_norm, pA2h, pA2l, n4); }
    {
        dim3 grid(LL / 128, DMODEL / 128);
        gemm_mma<<<grid, 256, MM_SMEM>>>(pA2h, pA2l, pW2h, pW2l, out, LL, DMODEL, INTER_);
    }
}

// round 6
// speedup vs baseline: 2.3806x; 1.1857x over previous
#include <cuda_runtime.h>
#include <cuda_bf16.h>
#include <math.h>
#include <stdint.h>

// ---------------- problem constants ----------------
#define HH      64
#define PP      64
#define NST     128
#define GG      8
#define DMODEL  2048
#define CSZ     256
#define LL      4096
#define INTER_  4096
#define CONVDIM_ 6144
#define PROJ_   10304
#define NCH     16
#define NBATCH  1024

// ---------------- fp32 scratch ----------------
__device__ float d_proj[(size_t)LL * PROJ_];
__device__ float d_conv[(size_t)LL * CONVDIM_];
__device__ float d_dt[(size_t)LL * HH];
__device__ float d_Acs[(size_t)HH * LL];
__device__ float d_states[(size_t)NBATCH * PP * NST];
__device__ float d_Y[(size_t)LL * INTER_];

// ---------------- bf16 hi/lo operand arrays ----------------
__device__ __nv_bfloat16 d_A1hi[(size_t)LL * DMODEL];
__device__ __nv_bfloat16 d_A1lo[(size_t)LL * DMODEL];
__device__ __nv_bfloat16 d_W1hi[(size_t)PROJ_ * DMODEL];
__device__ __nv_bfloat16 d_W1lo[(size_t)PROJ_ * DMODEL];
__device__ __nv_bfloat16 d_A2hi[(size_t)LL * INTER_];
__device__ __nv_bfloat16 d_A2lo[(size_t)LL * INTER_];
__device__ __nv_bfloat16 d_W2hi[(size_t)DMODEL * INTER_];
__device__ __nv_bfloat16 d_W2lo[(size_t)DMODEL * INTER_];

__device__ __nv_bfloat16 d_Bhi[(size_t)LL * 1024];   // B  [l][g*128+n]
__device__ __nv_bfloat16 d_Blo[(size_t)LL * 1024];
__device__ __nv_bfloat16 d_Chi2[(size_t)LL * 1024];  // C  [l][g*128+n]
__device__ __nv_bfloat16 d_Clo2[(size_t)LL * 1024];
__device__ __nv_bfloat16 d_BThi[(size_t)1024 * LL];  // B^T [g*128+n][l]
__device__ __nv_bfloat16 d_BTlo[(size_t)1024 * LL];
__device__ __nv_bfloat16 d_xThi[(size_t)INTER_ * LL];   // xdt^T   [h*64+p][l]
__device__ __nv_bfloat16 d_xTlo[(size_t)INTER_ * LL];
__device__ __nv_bfloat16 d_xdThi[(size_t)INTER_ * LL];  // (xdt*decay)^T
__device__ __nv_bfloat16 d_xdTlo[(size_t)INTER_ * LL];
__device__ __nv_bfloat16 d_pvhi[(size_t)NBATCH * PP * NST]; // prev [z][p][n]
__device__ __nv_bfloat16 d_pvlo[(size_t)NBATCH * PP * NST];

// ---------------- helpers ----------------
__device__ __forceinline__ uint32_t smem_u32(const void* p) {
    uint32_t a;
    asm("{ .reg .u64 t; cvta.to.shared.u64 t, %1; cvt.u32.u64 %0, t; }" : "=r"(a) : "l"(p));
    return a;
}
__device__ __forceinline__ void cpa16(uint32_t dst, const void* src) {
    asm volatile("cp.async.cg.shared.global [%0], [%1], 16;\n" :: "r"(dst), "l"(src));
}
#define CP_COMMIT() asm volatile("cp.async.commit_group;\n" ::: "memory")
#define CP_WAIT2()  asm volatile("cp.async.wait_group 2;\n" ::: "memory")
#define CP_WAIT1()  asm volatile("cp.async.wait_group 1;\n" ::: "memory")
#define CP_WAIT0()  asm volatile("cp.async.wait_group 0;\n" ::: "memory")

#define LDSM4(r, addr) \
    asm volatile("ldmatrix.sync.aligned.m8n8.x4.shared.b16 {%0,%1,%2,%3}, [%4];" \
                 : "=r"((r)[0]), "=r"((r)[1]), "=r"((r)[2]), "=r"((r)[3]) : "r"(addr))
#define MMA16816(d, a, b) \
    asm volatile("mma.sync.aligned.m16n8k16.row.col.f32.bf16.bf16.f32 " \
                 "{%0,%1,%2,%3}, {%4,%5,%6,%7}, {%8,%9}, {%0,%1,%2,%3};" \
                 : "+f"((d)[0]), "+f"((d)[1]), "+f"((d)[2]), "+f"((d)[3]) \
                 : "r"((a)[0]), "r"((a)[1]), "r"((a)[2]), "r"((a)[3]), \
                   "r"((b)[0]), "r"((b)[1]))

__device__ __forceinline__ void split2(float v, __nv_bfloat16& h, __nv_bfloat16& l) {
    h = __float2bfloat16_rn(v);
    l = __float2bfloat16_rn(v - __bfloat162float(h));
}

// ============================================================================
// Big split-bf16 GEMM: 4-stage cp.async pipeline, ONE barrier per K-chunk.
// ============================================================================
#define MM_STAGES 4
#define MM_ROWB   80
#define MM_ABYTES (128 * MM_ROWB)
#define MM_SSTAGE (2 * MM_ABYTES)
#define MM_SMEM   (MM_STAGES * MM_SSTAGE)   // 81920

__global__ __launch_bounds__(256) void gemm_mma(
    const __nv_bfloat16* __restrict__ Ahi, const __nv_bfloat16* __restrict__ Alo,
    const __nv_bfloat16* __restrict__ Bhi, const __nv_bfloat16* __restrict__ Blo,
    float* __restrict__ C, int M, int N, int K)
{
    extern __shared__ char smem[];
    const int tid  = threadIdx.x;
    const int wid  = tid >> 5;
    const int lane = tid & 31;
    const int m0 = blockIdx.x * 128;
    const int n0 = blockIdx.y * 128;
    const int wm = (wid & 3) * 32;
    const int wn = (wid >> 2) * 64;
    const uint32_t sbase = smem_u32(smem);

    const int KB = K >> 5;
    const int NC = 3 * KB;

    float acc[2][8][4];
#pragma unroll
    for (int i = 0; i < 2; i++)
#pragma unroll
        for (int j = 0; j < 8; j++)
#pragma unroll
            for (int t = 0; t < 4; t++) acc[i][j][t] = 0.f;

    const int it0 = tid, it1 = tid + 256;
    const int ar0 = it0 >> 2, ac0 = (it0 & 3) << 4;
    const int ar1 = it1 >> 2, ac1 = (it1 & 3) << 4;

    auto issue = [&](int j) {
        const int s = j & (MM_STAGES - 1);
        const uint32_t As = sbase + s * MM_SSTAGE;
        const uint32_t Bs = As + MM_ABYTES;
        const int seg = j / KB;
        const int kk = j - seg * KB;
        const __nv_bfloat16* Ag = (seg == 1) ? Alo : Ahi;
        const __nv_bfloat16* Bg = (seg == 2) ? Blo : Bhi;
        const size_t kof = (size_t)kk * 32;
        cpa16(As + ar0 * MM_ROWB + ac0, Ag + (size_t)(m0 + ar0) * K + kof + (ac0 >> 1));
        cpa16(As + ar1 * MM_ROWB + ac1, Ag + (size_t)(m0 + ar1) * K + kof + (ac1 >> 1));
        {
            int nn0 = n0 + ar0, nn1 = n0 + ar1;
            int p0 = (nn0 < N) ? 16 : 0;
            int p1 = (nn1 < N) ? 16 : 0;
            if (nn0 >= N) nn0 = 0;
            if (nn1 >= N) nn1 = 0;
            const void* g0 = Bg + (size_t)nn0 * K + kof + (ac0 >> 1);
            const void* g1 = Bg + (size_t)nn1 * K + kof + (ac1 >> 1);
            asm volatile("cp.async.cg.shared.global [%0], [%1], 16, %2;\n"
                         :: "r"(Bs + ar0 * MM_ROWB + ac0), "l"(g0), "r"(p0));
            asm volatile("cp.async.cg.shared.global [%0], [%1], 16, %2;\n"
                         :: "r"(Bs + ar1 * MM_ROWB + ac1), "l"(g1), "r"(p1));
        }
    };

    const int quad = lane >> 3, qj = lane & 7;

    auto compute = [&](int i) {
        const int s = i & (MM_STAGES - 1);
        const uint32_t As = sbase + s * MM_SSTAGE;
        const uint32_t Bs = As + MM_ABYTES;
#pragma unroll
        for (int k16 = 0; k16 < 2; k16++) {
            const int k0 = k16 * 16;
            uint32_t a[2][4];
#pragma unroll
            for (int mt = 0; mt < 2; mt++) {
                int row = wm + mt * 16 + ((quad & 1) ? 8 : 0) + qj;
                int kel = k0 + ((quad & 2) ? 8 : 0);
                LDSM4(a[mt], As + row * MM_ROWB + kel * 2);
            }
            uint32_t b[8][2];
#pragma unroll
            for (int np = 0; np < 4; np++) {
                int row = wn + np * 16 + ((quad & 2) ? 8 : 0) + qj;
                int kel = k0 + ((quad & 1) ? 8 : 0);
                uint32_t t[4];
                LDSM4(t, Bs + row * MM_ROWB + kel * 2);
                b[np * 2][0] = t[0]; b[np * 2][1] = t[1];
                b[np * 2 + 1][0] = t[2]; b[np * 2 + 1][1] = t[3];
            }
#pragma unroll
            for (int mt = 0; mt < 2; mt++)
#pragma unroll
                for (int nt = 0; nt < 8; nt++) MMA16816(acc[mt][nt], a[mt], b[nt]);
        }
    };

    issue(0); CP_COMMIT();
    issue(1); CP_COMMIT();
    // 4 stages + single barrier: issue(i+2) touches stage (i+2)%4 = (i-2)%4,
    // whose last reader compute(i-2) is separated by the previous iteration's barrier.
    for (int i = 0; i < NC; i++) {
        if (i + 2 < NC) issue(i + 2);
        CP_COMMIT();
        CP_WAIT2();
        __syncthreads();
        compute(i);
    }

    const int g = lane >> 2, t4 = lane & 3;
#pragma unroll
    for (int mt = 0; mt < 2; mt++)
#pragma unroll
        for (int nt = 0; nt < 8; nt++) {
            int m = m0 + wm + mt * 16 + g;
            int n = n0 + wn + nt * 8 + t4 * 2;
            if (n < N) {
                *(float2*)(C + (size_t)m * N + n) = make_float2(acc[mt][nt][0], acc[mt][nt][1]);
                *(float2*)(C + (size_t)(m + 8) * N + n) = make_float2(acc[mt][nt][2], acc[mt][nt][3]);
            }
        }
}

// ============================================================================
// fp32 -> bf16 hi/lo split
// ============================================================================
__global__ void cvt_kernel(const float* __restrict__ src, __nv_bfloat16* __restrict__ hi,
                           __nv_bfloat16* __restrict__ lo, int n4) {
    int i = blockIdx.x * blockDim.x + threadIdx.x;
    if (i >= n4) return;
    float4 v = ((const float4*)src)[i];
    __nv_bfloat16 h0, h1, h2, h3, l0, l1, l2, l3;
    split2(v.x, h0, l0); split2(v.y, h1, l1);
    split2(v.z, h2, l2); split2(v.w, h3, l3);
    ((__nv_bfloat162*)hi)[2 * i]     = __nv_bfloat162(h0, h1);
    ((__nv_bfloat162*)hi)[2 * i + 1] = __nv_bfloat162(h2, h3);
    ((__nv_bfloat162*)lo)[2 * i]     = __nv_bfloat162(l0, l1);
    ((__nv_bfloat162*)lo)[2 * i + 1] = __nv_bfloat162(l2, l3);
}

// ============================================================================
// elementwise / scan kernels
// ============================================================================
__global__ void dt_kernel(const float* __restrict__ dt_bias) {
    int id = blockIdx.x * blockDim.x + threadIdx.x;
    if (id >= LL * HH) return;
    int l = id >> 6, h = id & 63;
    float v = d_proj[(size_t)l * PROJ_ + INTER_ + CONVDIM_ + h] + dt_bias[h];
    float sp = (v > 20.f) ? v : log1pf(expf(v));
    d_dt[id] = sp;
}

__global__ void acs_kernel(const float* __restrict__ A_log) {
    int t = blockIdx.x * blockDim.x + threadIdx.x;
    if (t >= NCH * HH) return;
    int h = t & 63, c = t >> 6;
    float Ah = -expf(A_log[h]);
    float run = 0.f;
    for (int s = 0; s < CSZ; s++) {
        run += d_dt[(size_t)(c * CSZ + s) * HH + h] * Ah;
        d_Acs[(size_t)h * LL + c * CSZ + s] = run;
    }
}

// conv + silu; ALSO writes B/C bf16 hi/lo splits inline (fuses old cvt_bc)
__global__ void conv_kernel(const float* __restrict__ conv_w, const float* __restrict__ conv_b) {
    int id = blockIdx.x * blockDim.x + threadIdx.x;
    if (id >= LL * CONVDIM_) return;
    int l = id / CONVDIM_, cc = id % CONVDIM_;
    float acc = conv_b[cc];
#pragma unroll
    for (int k = 0; k < 4; k++) {
        int li = l - 3 + k;
        if (li >= 0) acc += conv_w[cc * 4 + k] * d_proj[(size_t)li * PROJ_ + INTER_ + cc];
    }
    float v = acc / (1.f + __expf(-acc));
    d_conv[id] = v;
    if (cc >= INTER_) {
        int j = cc - INTER_;
        __nv_bfloat16 h, lo;
        split2(v, h, lo);
        if (j < 1024) { d_Bhi[(size_t)l * 1024 + j] = h; d_Blo[(size_t)l * 1024 + j] = lo; }
        else { d_Chi2[(size_t)l * 1024 + j - 1024] = h; d_Clo2[(size_t)l * 1024 + j - 1024] = lo; }
    }
}

// B^T hi/lo [g*128+n][l]
__global__ void btrans_kernel() {
    __shared__ float tile[32][33];
    int x = blockIdx.x * 32 + threadIdx.x;   // gn
    int y0 = blockIdx.y * 32;                // l
    for (int j = threadIdx.y; j < 32; j += 8)
        tile[j][threadIdx.x] = d_conv[(size_t)(y0 + j) * CONVDIM_ + INTER_ + x];
    __syncthreads();
    int l = y0 + threadIdx.x;
    for (int j = threadIdx.y; j < 32; j += 8) {
        int gn = blockIdx.x * 32 + j;
        __nv_bfloat16 h, lo;
        split2(tile[threadIdx.x][j], h, lo);
        d_BThi[(size_t)gn * LL + l] = h;
        d_BTlo[(size_t)gn * LL + l] = lo;
    }
}

// xdt^T and (xdt*decay)^T hi/lo, computing xdt = conv*dt on the fly
__global__ void xtrans_kernel() {
    __shared__ float tile[32][33];
    int x = blockIdx.x * 32 + threadIdx.x;   // hp
    int y0 = blockIdx.y * 32;                // l
    int hload = x >> 6;
    for (int j = threadIdx.y; j < 32; j += 8)
        tile[j][threadIdx.x] = d_conv[(size_t)(y0 + j) * CONVDIM_ + x] *
                               d_dt[(size_t)(y0 + j) * HH + hload];
    __syncthreads();
    int l = y0 + threadIdx.x;
    int lastl = l | (CSZ - 1);
    for (int j = threadIdx.y; j < 32; j += 8) {
        int hp = blockIdx.x * 32 + j;
        int h = hp >> 6;
        float v = tile[threadIdx.x][j];
        __nv_bfloat16 hh, ll;
        split2(v, hh, ll);
        d_xThi[(size_t)hp * LL + l] = hh;
        d_xTlo[(size_t)hp * LL + l] = ll;
        float dec = __expf(d_Acs[(size_t)h * LL + lastl] - d_Acs[(size_t)h * LL + l]);
        split2(v * dec, hh, ll);
        d_xdThi[(size_t)hp * LL + l] = hh;
        d_xdTlo[(size_t)hp * LL + l] = ll;
    }
}

// inter-chunk recurrence; writes prev splits directly
__global__ void state_scan_kernel() {
    int t = blockIdx.x * blockDim.x + threadIdx.x;
    if (t >= HH * PP * NST) return;
    int n = t & 127, p = (t >> 7) & 63, h = t >> 13;
    float prev = 0.f;
#pragma unroll
    for (int c = 0; c < NCH; c++) {
        size_t idx = ((size_t)(c * HH + h) * PP + p) * NST + n;
        __nv_bfloat16 hh, ll;
        split2(prev, hh, ll);
        d_pvhi[idx] = hh;
        d_pvlo[idx] = ll;
        float cd = __expf(d_Acs[(size_t)h * LL + c * CSZ + 255]);
        prev = prev * cd + d_states[idx];
    }
}

// ============================================================================
// Fused scores + Y_diag kernel
// ============================================================================
#define CK_ROWB 80
#define CK_STAGE (4 * 128 * CK_ROWB)
#define CK_SROW 272
#define CK_SOFF (2 * CK_STAGE)
#define CK_SBYT (128 * CK_SROW)
#define CK_XOFF (CK_SOFF + 2 * CK_SBYT)
#define CK_XBYT (64 * CK_SROW)
#define CK_SMEM (CK_XOFF + 2 * CK_XBYT)

__global__ __launch_bounds__(256) void chunk_kernel() {
    const int lhalf = blockIdx.x;
    const int z = blockIdx.y;
    const int c = z >> 6, h = z & 63, g = h >> 3;
    extern __shared__ char sm[];
    const uint32_t sb = smem_u32(sm);
    const int tid = threadIdx.x;
    const int wid = tid >> 5, lane = tid & 31;
    const int quad = lane >> 3, qj = lane & 7;
    const int wy = wid & 3, wx = wid >> 2;
    const int l0 = c * CSZ + lhalf * 128;

    float yacc[2][4][4];
#pragma unroll
    for (int i = 0; i < 2; i++)
#pragma unroll
        for (int j = 0; j < 4; j++)
#pragma unroll
            for (int t = 0; t < 4; t++) yacc[i][j][t] = 0.f;

    const float* acsH = d_Acs + (size_t)h * LL + c * CSZ;

    for (int sh = 0; sh <= lhalf; sh++) {
        const int s0 = c * CSZ + sh * 128;
        float acc[2][8][4];
#pragma unroll
        for (int i = 0; i < 2; i++)
#pragma unroll
            for (int j = 0; j < 8; j++)
#pragma unroll
                for (int t = 0; t < 4; t++) acc[i][j][t] = 0.f;

#pragma unroll
        for (int rep = 0; rep < 4; rep++) {
            int slot = tid + rep * 256;
            int row = slot >> 4, c16 = (slot & 15) * 16;
            size_t off = (size_t)(h * 64 + row) * LL + s0 + (c16 >> 1);
            cpa16(sb + CK_XOFF + row * CK_SROW + c16, d_xThi + off);
            cpa16(sb + CK_XOFF + CK_XBYT + row * CK_SROW + c16, d_xTlo + off);
        }
        {
            const uint32_t base = sb + 0 * CK_STAGE;
#pragma unroll
            for (int rep = 0; rep < 2; rep++) {
                int slot = tid + rep * 256;
                int row = slot >> 2, c16 = (slot & 3) * 16;
                int kofe = 0 * 32 + (c16 >> 1);
                size_t crow = (size_t)(l0 + row) * 1024 + g * 128 + kofe;
                size_t brow = (size_t)(s0 + row) * 1024 + g * 128 + kofe;
                cpa16(base + row * CK_ROWB + c16, d_Chi2 + crow);
                cpa16(base + 10240 + row * CK_ROWB + c16, d_Clo2 + crow);
                cpa16(base + 20480 + row * CK_ROWB + c16, d_Bhi + brow);
                cpa16(base + 30720 + row * CK_ROWB + c16, d_Blo + brow);
            }
        }
        CP_COMMIT();
        {
            const uint32_t base = sb + 1 * CK_STAGE;
#pragma unroll
            for (int rep = 0; rep < 2; rep++) {
                int slot = tid + rep * 256;
                int row = slot >> 2, c16 = (slot & 3) * 16;
                int kofe = 1 * 32 + (c16 >> 1);
                size_t crow = (size_t)(l0 + row) * 1024 + g * 128 + kofe;
                size_t brow = (size_t)(s0 + row) * 1024 + g * 128 + kofe;
                cpa16(base + row * CK_ROWB + c16, d_Chi2 + crow);
                cpa16(base + 10240 + row * CK_ROWB + c16, d_Clo2 + crow);
                cpa16(base + 20480 + row * CK_ROWB + c16, d_Bhi + brow);
                cpa16(base + 30720 + row * CK_ROWB + c16, d_Blo + brow);
            }
        }
        CP_COMMIT();

        for (int kc = 0; kc < 4; kc++) {
            if (kc == 3) CP_WAIT0(); else CP_WAIT1();
            __syncthreads();
            {
                const uint32_t base = sb + (kc & 1) * CK_STAGE;
                const uint32_t Ch = base, Cl = base + 10240, Bh = base + 20480, Bl = base + 30720;
#pragma unroll
                for (int k16 = 0; k16 < 2; k16++) {
                    const int k0 = k16 * 16;
                    uint32_t ah[2][4], al_[2][4];
#pragma unroll
                    for (int mt = 0; mt < 2; mt++) {
                        int row = wy * 32 + mt * 16 + ((quad & 1) ? 8 : 0) + qj;
                        int kel = k0 + ((quad & 2) ? 8 : 0);
                        LDSM4(ah[mt], Ch + row * CK_ROWB + kel * 2);
                        LDSM4(al_[mt], Cl + row * CK_ROWB + kel * 2);
                    }
                    uint32_t bh[8][2], bl[8][2];
#pragma unroll
                    for (int np = 0; np < 4; np++) {
                        int row = wx * 64 + np * 16 + ((quad & 2) ? 8 : 0) + qj;
                        int kel = k0 + ((quad & 1) ? 8 : 0);
                        uint32_t t[4];
                        LDSM4(t, Bh + row * CK_ROWB + kel * 2);
                        bh[np * 2][0] = t[0]; bh[np * 2][1] = t[1];
                        bh[np * 2 + 1][0] = t[2]; bh[np * 2 + 1][1] = t[3];
                        LDSM4(t, Bl + row * CK_ROWB + kel * 2);
                        bl[np * 2][0] = t[0]; bl[np * 2][1] = t[1];
                        bl[np * 2 + 1][0] = t[2]; bl[np * 2 + 1][1] = t[3];
                    }
#pragma unroll
                    for (int mt = 0; mt < 2; mt++)
#pragma unroll
                        for (int nt = 0; nt < 8; nt++) {
                            MMA16816(acc[mt][nt], ah[mt], bh[nt]);
                            MMA16816(acc[mt][nt], al_[mt], bh[nt]);
                            MMA16816(acc[mt][nt], ah[mt], bl[nt]);
                        }
                }
            }
            __syncthreads();
            if (kc + 2 < 4) {
                const uint32_t base = sb + ((kc + 2) & 1) * CK_STAGE;
#pragma unroll
                for (int rep = 0; rep < 2; rep++) {
                    int slot = tid + rep * 256;
                    int row = slot >> 2, c16 = (slot & 3) * 16;
                    int kofe = (kc + 2) * 32 + (c16 >> 1);
                    size_t crow = (size_t)(l0 + row) * 1024 + g * 128 + kofe;
                    size_t brow = (size_t)(s0 + row) * 1024 + g * 128 + kofe;
                    cpa16(base + row * CK_ROWB + c16, d_Chi2 + crow);
                    cpa16(base + 10240 + row * CK_ROWB + c16, d_Clo2 + crow);
                    cpa16(base + 20480 + row * CK_ROWB + c16, d_Bhi + brow);
                    cpa16(base + 30720 + row * CK_ROWB + c16, d_Blo + brow);
                }
                CP_COMMIT();
            }
        }

        {
            const bool diag = (sh == lhalf);
            char* Sh = sm + CK_SOFF;
            char* Sl = sm + CK_SOFF + CK_SBYT;
#pragma unroll
            for (int mt = 0; mt < 2; mt++) {
                int r0 = wy * 32 + mt * 16 + (lane >> 2);
#pragma unroll
                for (int half = 0; half < 2; half++) {
                    int r = r0 + half * 8;
                    float al = acsH[lhalf * 128 + r];
#pragma unroll
                    for (int nt = 0; nt < 8; nt++) {
                        int cc = wx * 64 + nt * 8 + (lane & 3) * 2;
                        float v0 = acc[mt][nt][half * 2 + 0];
                        float v1 = acc[mt][nt][half * 2 + 1];
                        float as0 = acsH[sh * 128 + cc];
                        float as1 = acsH[sh * 128 + cc + 1];
                        v0 = (!diag || (cc <= r)) ? v0 * __expf(al - as0) : 0.f;
                        v1 = (!diag || (cc + 1 <= r)) ? v1 * __expf(al - as1) : 0.f;
                        __nv_bfloat16 h0, h1, q0, q1;
                        split2(v0, h0, q0);
                        split2(v1, h1, q1);
                        *(__nv_bfloat162*)(Sh + r * CK_SROW + cc * 2) = __nv_bfloat162(h0, h1);
                        *(__nv_bfloat162*)(Sl + r * CK_SROW + cc * 2) = __nv_bfloat162(q0, q1);
                    }
                }
            }
        }
        __syncthreads();

        {
            const uint32_t Sh = sb + CK_SOFF, Sl = sb + CK_SOFF + CK_SBYT;
            const uint32_t Xh = sb + CK_XOFF, Xl = sb + CK_XOFF + CK_XBYT;
#pragma unroll 2
            for (int k16 = 0; k16 < 8; k16++) {
                const int k0 = k16 * 16;
                uint32_t ah[2][4], al_[2][4];
#pragma unroll
                for (int mt = 0; mt < 2; mt++) {
                    int row = wy * 32 + mt * 16 + ((quad & 1) ? 8 : 0) + qj;
                    int kel = k0 + ((quad & 2) ? 8 : 0);
                    LDSM4(ah[mt], Sh + row * CK_SROW + kel * 2);
                    LDSM4(al_[mt], Sl + row * CK_SROW + kel * 2);
                }
                uint32_t bh[4][2], bl[4][2];
#pragma unroll
                for (int np = 0; np < 2; np++) {
                    int row = wx * 32 + np * 16 + ((quad & 2) ? 8 : 0) + qj;
                    int kel = k0 + ((quad & 1) ? 8 : 0);
                    uint32_t t[4];
                    LDSM4(t, Xh + row * CK_SROW + kel * 2);
                    bh[np * 2][0] = t[0]; bh[np * 2][1] = t[1];
                    bh[np * 2 + 1][0] = t[2]; bh[np * 2 + 1][1] = t[3];
                    LDSM4(t, Xl + row * CK_SROW + kel * 2);
                    bl[np * 2][0] = t[0]; bl[np * 2][1] = t[1];
                    bl[np * 2 + 1][0] = t[2]; bl[np * 2 + 1][1] = t[3];
                }
#pragma unroll
                for (int mt = 0; mt < 2; mt++)
#pragma unroll
                    for (int nt = 0; nt < 4; nt++) {
                        MMA16816(yacc[mt][nt], ah[mt], bh[nt]);
                        MMA16816(yacc[mt][nt], al_[mt], bh[nt]);
                        MMA16816(yacc[mt][nt], ah[mt], bl[nt]);
                    }
            }
        }
        __syncthreads();
    }

#pragma unroll
    for (int mt = 0; mt < 2; mt++)
#pragma unroll
        for (int nt = 0; nt < 4; nt++) {
            int r = wy * 32 + mt * 16 + (lane >> 2);
            int gl = l0 + r;
            int p = wx * 32 + nt * 8 + (lane & 3) * 2;
            *(float2*)(d_Y + (size_t)gl * INTER_ + h * 64 + p) =
                make_float2(yacc[mt][nt][0], yacc[mt][nt][1]);
            *(float2*)(d_Y + (size_t)(gl + 8) * INTER_ + h * 64 + p) =
                make_float2(yacc[mt][nt][2], yacc[mt][nt][3]);
        }
}

// ============================================================================
// states kernel
// ============================================================================
#define ST_STRIDE 30720
#define ST_SMEM   (2 * ST_STRIDE)

__global__ __launch_bounds__(256) void states_mma_kernel() {
    const int z = blockIdx.x;
    const int c = z >> 6, h = z & 63, g = h >> 3;
    extern __shared__ char sm[];
    const uint32_t sb = smem_u32(sm);
    const int tid = threadIdx.x;
    const int wid = tid >> 5, lane = tid & 31;
    const int quad = lane >> 3, qj = lane & 7;
    const int wy = wid & 1, wx = wid >> 1;

    float acc[2][4][4];
#pragma unroll
    for (int i = 0; i < 2; i++)
#pragma unroll
        for (int j = 0; j < 4; j++)
#pragma unroll
            for (int t = 0; t < 4; t++) acc[i][j][t] = 0.f;

    auto issue = [&](int kc) {
        const uint32_t base = sb + (kc & 1) * ST_STRIDE;
        {
            int slot = tid;
            int row = slot >> 2, c16 = (slot & 3) * 16;
            size_t off = (size_t)(h * 64 + row) * LL + c * CSZ + kc * 32 + (c16 >> 1);
            cpa16(base + row * 80 + c16, d_xdThi + off);
            cpa16(base + 5120 + row * 80 + c16, d_xdTlo + off);
        }
#pragma unroll
        for (int rep = 0; rep < 2; rep++) {
            int slot = tid + rep * 256;
            int row = slot >> 2, c16 = (slot & 3) * 16;
            size_t off = (size_t)(g * 128 + row) * LL + c * CSZ + kc * 32 + (c16 >> 1);
            cpa16(base + 10240 + row * 80 + c16, d_BThi + off);
            cpa16(base + 20480 + row * 80 + c16, d_BTlo + off);
        }
    };

    issue(0); CP_COMMIT();
    issue(1); CP_COMMIT();
    for (int kc = 0; kc < 8; kc++) {
        if (kc == 7) CP_WAIT0(); else CP_WAIT1();
        __syncthreads();
        {
            const uint32_t base = sb + (kc & 1) * ST_STRIDE;
            const uint32_t Ah = base, Al = base + 5120, Bh = base + 10240, Bl = base + 20480;
#pragma unroll
            for (int k16 = 0; k16 < 2; k16++) {
                const int k0 = k16 * 16;
                uint32_t ah[2][4], al_[2][4];
#pragma unroll
                for (int mt = 0; mt < 2; mt++) {
                    int row = wy * 32 + mt * 16 + ((quad & 1) ? 8 : 0) + qj;
                    int kel = k0 + ((quad & 2) ? 8 : 0);
                    LDSM4(ah[mt], Ah + row * 80 + kel * 2);
                    LDSM4(al_[mt], Al + row * 80 + kel * 2);
                }
                uint32_t bh[4][2], bl[4][2];
#pragma unroll
                for (int np = 0; np < 2; np++) {
                    int row = wx * 32 + np * 16 + ((quad & 2) ? 8 : 0) + qj;
                    int kel = k0 + ((quad & 1) ? 8 : 0);
                    uint32_t t[4];
                    LDSM4(t, Bh + row * 80 + kel * 2);
                    bh[np * 2][0] = t[0]; bh[np * 2][1] = t[1];
                    bh[np * 2 + 1][0] = t[2]; bh[np * 2 + 1][1] = t[3];
                    LDSM4(t, Bl + row * 80 + kel * 2);
                    bl[np * 2][0] = t[0]; bl[np * 2][1] = t[1];
                    bl[np * 2 + 1][0] = t[2]; bl[np * 2 + 1][1] = t[3];
                }
#pragma unroll
                for (int mt = 0; mt < 2; mt++)
#pragma unroll
                    for (int nt = 0; nt < 4; nt++) {
                        MMA16816(acc[mt][nt], ah[mt], bh[nt]);
                        MMA16816(acc[mt][nt], al_[mt], bh[nt]);
                        MMA16816(acc[mt][nt], ah[mt], bl[nt]);
                    }
            }
        }
        __syncthreads();
        if (kc + 2 < 8) { issue(kc + 2); CP_COMMIT(); }
    }

#pragma unroll
    for (int mt = 0; mt < 2; mt++)
#pragma unroll
        for (int nt = 0; nt < 4; nt++) {
            int p = wy * 32 + mt * 16 + (lane >> 2);
            int n = wx * 32 + nt * 8 + (lane & 3) * 2;
            *(float2*)(d_states + (size_t)z * 8192 + p * 128 + n) =
                make_float2(acc[mt][nt][0], acc[mt][nt][1]);
            *(float2*)(d_states + (size_t)z * 8192 + (p + 8) * 128 + n) =
                make_float2(acc[mt][nt][2], acc[mt][nt][3]);
        }
}

// ============================================================================
// yoff kernel
// ============================================================================
__global__ __launch_bounds__(256) void yoff_mma_kernel(const float* __restrict__ Dvec) {
    const int lhalf = blockIdx.x;
    const int z = blockIdx.y;
    const int c = z >> 6, h = z & 63, g = h >> 3;
    extern __shared__ char sm[];
    const uint32_t sb = smem_u32(sm);
    const int tid = threadIdx.x;
    const int wid = tid >> 5, lane = tid & 31;
    const int quad = lane >> 3, qj = lane & 7;
    const int wy = wid & 3, wx = wid >> 2;
    const int l0 = c * CSZ + lhalf * 128;

    float acc[2][4][4];
#pragma unroll
    for (int i = 0; i < 2; i++)
#pragma unroll
        for (int j = 0; j < 4; j++)
#pragma unroll
            for (int t = 0; t < 4; t++) acc[i][j][t] = 0.f;

    auto issue = [&](int kc) {
        const uint32_t base = sb + (kc & 1) * ST_STRIDE;
#pragma unroll
        for (int rep = 0; rep < 2; rep++) {
            int slot = tid + rep * 256;
            int row = slot >> 2, c16 = (slot & 3) * 16;
            size_t off = (size_t)(l0 + row) * 1024 + g * 128 + kc * 32 + (c16 >> 1);
            cpa16(base + row * 80 + c16, d_Chi2 + off);
            cpa16(base + 10240 + row * 80 + c16, d_Clo2 + off);
        }
        {
            int slot = tid;
            int row = slot >> 2, c16 = (slot & 3) * 16;
            size_t off = (size_t)z * 8192 + row * 128 + kc * 32 + (c16 >> 1);
            cpa16(base + 20480 + row * 80 + c16, d_pvhi + off);
            cpa16(base + 25600 + row * 80 + c16, d_pvlo + off);
        }
    };

    issue(0); CP_COMMIT();
    issue(1); CP_COMMIT();
    for (int kc = 0; kc < 4; kc++) {
        if (kc == 3) CP_WAIT0(); else CP_WAIT1();
        __syncthreads();
        {
            const uint32_t base = sb + (kc & 1) * ST_STRIDE;
            const uint32_t Ah = base, Al = base + 10240, Bh = base + 20480, Bl = base + 25600;
#pragma unroll
            for (int k16 = 0; k16 < 2; k16++) {
                const int k0 = k16 * 16;
                uint32_t ah[2][4], al_[2][4];
#pragma unroll
                for (int mt = 0; mt < 2; mt++) {
                    int row = wy * 32 + mt * 16 + ((quad & 1) ? 8 : 0) + qj;
                    int kel = k0 + ((quad & 2) ? 8 : 0);
                    LDSM4(ah[mt], Ah + row * 80 + kel * 2);
                    LDSM4(al_[mt], Al + row * 80 + kel * 2);
                }
                uint32_t bh[4][2], bl[4][2];
#pragma unroll
                for (int np = 0; np < 2; np++) {
                    int row = wx * 32 + np * 16 + ((quad & 2) ? 8 : 0) + qj;
                    int kel = k0 + ((quad & 1) ? 8 : 0);
                    uint32_t t[4];
                    LDSM4(t, Bh + row * 80 + kel * 2);
                    bh[np * 2][0] = t[0]; bh[np * 2][1] = t[1];
                    bh[np * 2 + 1][0] = t[2]; bh[np * 2 + 1][1] = t[3];
                    LDSM4(t, Bl + row * 80 + kel * 2);
                    bl[np * 2][0] = t[0]; bl[np * 2][1] = t[1];
                    bl[np * 2 + 1][0] = t[2]; bl[np * 2 + 1][1] = t[3];
                }
#pragma unroll
                for (int mt = 0; mt < 2; mt++)
#pragma unroll
                    for (int nt = 0; nt < 4; nt++) {
                        MMA16816(acc[mt][nt], ah[mt], bh[nt]);
                        MMA16816(acc[mt][nt], al_[mt], bh[nt]);
                        MMA16816(acc[mt][nt], ah[mt], bl[nt]);
                    }
            }
        }
        __syncthreads();
        if (kc + 2 < 4) { issue(kc + 2); CP_COMMIT(); }
    }

    const float Dv = Dvec[h];
    const float* acsH = d_Acs + (size_t)h * LL;
#pragma unroll
    for (int mt = 0; mt < 2; mt++)
#pragma unroll
        for (int nt = 0; nt < 4; nt++) {
            int r = wy * 32 + mt * 16 + (lane >> 2);
            int p = wx * 32 + nt * 8 + (lane & 3) * 2;
#pragma unroll
            for (int half = 0; half < 2; half++) {
                int gl = l0 + r + half * 8;
                float sd = __expf(acsH[gl]);
                float2 y = *(float2*)(d_Y + (size_t)gl * INTER_ + h * 64 + p);
                float2 x = *(float2*)(d_conv + (size_t)gl * CONVDIM_ + h * 64 + p);
                y.x += acc[mt][nt][half * 2 + 0] * sd + Dv * x.x;
                y.y += acc[mt][nt][half * 2 + 1] * sd + Dv * x.y;
                *(float2*)(d_Y + (size_t)gl * INTER_ + h * 64 + p) = y;
            }
        }
}

// ============================================================================
// gated group RMS norm — writes GEMM2 A-operand splits directly
// ============================================================================
__global__ __launch_bounds__(256) void norm_kernel(const float* __restrict__ norm_weight) {
    __shared__ float gbuf[INTER_];
    __shared__ float rs[GG];
    int l = blockIdx.x, tid = threadIdx.x;
    for (int i = tid; i < INTER_; i += 256) {
        float y = d_Y[(size_t)l * INTER_ + i];
        float gt = d_proj[(size_t)l * PROJ_ + i];
        float sg = 1.f / (1.f + __expf(-gt));
        gbuf[i] = y * gt * sg;
    }
    __syncthreads();
    int w = tid >> 5, lane = tid & 31;
    float ss = 0.f;
    for (int j = lane; j < 512; j += 32) { float v = gbuf[w * 512 + j]; ss += v * v; }
#pragma unroll
    for (int o = 16; o > 0; o >>= 1) ss += __shfl_xor_sync(0xffffffffu, ss, o);
    if (lane == 0) rs[w] = rsqrtf(ss * (1.f / 512.f) + 1e-5f);
    __syncthreads();
    for (int i = tid; i < INTER_; i += 256) {
        float v = gbuf[i] * rs[i >> 9] * norm_weight[i];
        __nv_bfloat16 h, lo;
        split2(v, h, lo);
        d_A2hi[(size_t)l * INTER_ + i] = h;
        d_A2lo[(size_t)l * INTER_ + i] = lo;
    }
}

// ============================================================================
extern "C" void kernel_launch(void* const* d_in, const int* in_sizes, int n_in,
                              void* d_out, int out_size) {
    (void)in_sizes; (void)n_in; (void)out_size;
    const float* hidden      = (const float*)d_in[0];
    const float* W_in        = (const float*)d_in[1];
    const float* conv_w      = (const float*)d_in[2];
    const float* conv_b      = (const float*)d_in[3];
    const float* dt_bias     = (const float*)d_in[4];
    const float* A_log       = (const float*)d_in[5];
    const float* Dvec        = (const float*)d_in[6];
    const float* norm_weight = (const float*)d_in[7];
    const float* W_out       = (const float*)d_in[8];
    float* out = (float*)d_out;

    float *p_proj = nullptr;
    __nv_bfloat16 *pA1h, *pA1l, *pW1h, *pW1l, *pA2h, *pA2l, *pW2h, *pW2l;
    cudaGetSymbolAddress((void**)&p_proj, d_proj);
    cudaGetSymbolAddress((void**)&pA1h, d_A1hi);
    cudaGetSymbolAddress((void**)&pA1l, d_A1lo);
    cudaGetSymbolAddress((void**)&pW1h, d_W1hi);
    cudaGetSymbolAddress((void**)&pW1l, d_W1lo);
    cudaGetSymbolAddress((void**)&pA2h, d_A2hi);
    cudaGetSymbolAddress((void**)&pA2l, d_A2lo);
    cudaGetSymbolAddress((void**)&pW2h, d_W2hi);
    cudaGetSymbolAddress((void**)&pW2l, d_W2lo);

    cudaFuncSetAttribute(gemm_mma, cudaFuncAttributeMaxDynamicSharedMemorySize, MM_SMEM);
    cudaFuncSetAttribute(chunk_kernel, cudaFuncAttributeMaxDynamicSharedMemorySize, CK_SMEM);
    cudaFuncSetAttribute(states_mma_kernel, cudaFuncAttributeMaxDynamicSharedMemorySize, ST_SMEM);
    cudaFuncSetAttribute(yoff_mma_kernel, cudaFuncAttributeMaxDynamicSharedMemorySize, ST_SMEM);

    // 0) splits for big GEMM operands
    { int n4 = (LL * DMODEL) / 4;    cvt_kernel<<<(n4 + 255) / 256, 256>>>(hidden, pA1h, pA1l, n4); }
    { int n4 = (PROJ_ * DMODEL) / 4; cvt_kernel<<<(n4 + 255) / 256, 256>>>(W_in, pW1h, pW1l, n4); }
    { int n4 = (DMODEL * INTER_) / 4; cvt_kernel<<<(n4 + 255) / 256, 256>>>(W_out, pW2h, pW2l, n4); }
    // 1) input projection
    {
        dim3 grid(LL / 128, (PROJ_ + 127) / 128);
        gemm_mma<<<grid, 256, MM_SMEM>>>(pA1h, pA1l, pW1h, pW1l, p_proj, LL, PROJ_, DMODEL);
    }
    // 2-4) dt, cumsum, conv(+BC splits)
    dt_kernel<<<(LL * HH) / 256, 256>>>(dt_bias);
    acs_kernel<<<(NCH * HH + 255) / 256, 256>>>(A_log);
    conv_kernel<<<(LL * CONVDIM_) / 256, 256>>>(conv_w, conv_b);
    // 5) transposed operand prep
    { dim3 grid(1024 / 32, LL / 32); btrans_kernel<<<grid, dim3(32, 8)>>>(); }
    { dim3 grid(INTER_ / 32, LL / 32); xtrans_kernel<<<grid, dim3(32, 8)>>>(); }
    // 6) fused scores + Y_diag
    chunk_kernel<<<dim3(2, NBATCH), 256, CK_SMEM>>>();
    // 7) states + scan(+prev splits)
    states_mma_kernel<<<NBATCH, 256, ST_SMEM>>>();
    state_scan_kernel<<<(HH * PP * NST) / 256, 256>>>();
    // 8) Y_off + combine
    yoff_mma_kernel<<<dim3(2, NBATCH), 256, ST_SMEM>>>(Dvec);
    // 9) norm (+A2 splits)
    norm_kernel<<<LL, 256>>>(norm_weight);
    // 10) output projection
    {
        dim3 grid(LL / 128, DMODEL / 128);
        gemm_mma<<<grid, 256, MM_SMEM>>>(pA2h, pA2l, pW2h, pW2l, out, LL, DMODEL, INTER_);
    }
}